// round 14
// baseline (speedup 1.0000x reference)
#include <cuda_runtime.h>
#include <cuda_bf16.h>
#include <cstdint>
#include <math.h>

// Problem constants
#define BB 2
#define SS 2048
#define DD 1024
#define HH 16
#define DHH 64
#define ROWS (BB*SS)        // 4096
#define EPSF 1e-5f

// ======================= scratch (device globals) =======================
__device__ float g_x1  [(size_t)ROWS*DD];

// split-bf16 activations (hi/lo)
__device__ __nv_bfloat16 g_a1h[(size_t)ROWS*DD],   g_a1l[(size_t)ROWS*DD];
__device__ __nv_bfloat16 g_ath[(size_t)ROWS*DD],   g_atl[(size_t)ROWS*DD];
__device__ __nv_bfloat16 g_l2h[(size_t)ROWS*DD],   g_l2l[(size_t)ROWS*DD];
__device__ __nv_bfloat16 g_gh [(size_t)ROWS*2*DD], g_gl [(size_t)ROWS*2*DD];

// split-bf16 Q/K head-layout [bh][s][dh], V transposed [bh][dh][s]
__device__ __nv_bfloat16 g_qh [(size_t)ROWS*DD], g_ql [(size_t)ROWS*DD];
__device__ __nv_bfloat16 g_kh [(size_t)ROWS*DD], g_kl [(size_t)ROWS*DD];
__device__ __nv_bfloat16 g_vth[(size_t)ROWS*DD], g_vtl[(size_t)ROWS*DD];

// transposed split-bf16 weights: [N, K] K-major
__device__ __nv_bfloat16 g_wqh[(size_t)DD*DD], g_wql[(size_t)DD*DD];
__device__ __nv_bfloat16 g_wkh[(size_t)DD*DD], g_wkl[(size_t)DD*DD];
__device__ __nv_bfloat16 g_wvh[(size_t)DD*DD], g_wvl[(size_t)DD*DD];
__device__ __nv_bfloat16 g_woh[(size_t)DD*DD], g_wol[(size_t)DD*DD];
__device__ __nv_bfloat16 g_w1h[(size_t)DD*4*DD], g_w1l[(size_t)DD*4*DD];
__device__ __nv_bfloat16 g_w2h[(size_t)2*DD*DD], g_w2l[(size_t)2*DD*DD];

__device__ __forceinline__ void bf16split(float v, __nv_bfloat16& h, __nv_bfloat16& l){
    h = __float2bfloat16(v);
    l = __float2bfloat16(v - __bfloat162float(h));
}
// split a float pair into packed bf16x2 hi/lo words (low half = first elem)
__device__ __forceinline__ void split2(float a, float b, uint32_t& hi, uint32_t& lo){
    __nv_bfloat16 ha = __float2bfloat16(a), hb = __float2bfloat16(b);
    float ra = a - __bfloat162float(ha), rb = b - __bfloat162float(hb);
    __nv_bfloat16 la = __float2bfloat16(ra), lb = __float2bfloat16(rb);
    hi = ((uint32_t)__bfloat16_as_ushort(hb) << 16) | (uint32_t)__bfloat16_as_ushort(ha);
    lo = ((uint32_t)__bfloat16_as_ushort(lb) << 16) | (uint32_t)__bfloat16_as_ushort(la);
}

// m16n8k16 bf16 MMA, fp32 accumulate (baseline PTX, works on non-'a' targets)
__device__ __forceinline__ void mma16816(float* c, const uint32_t* a, const uint32_t* b){
    asm volatile(
        "mma.sync.aligned.m16n8k16.row.col.f32.bf16.bf16.f32 "
        "{%0,%1,%2,%3}, {%4,%5,%6,%7}, {%8,%9}, {%0,%1,%2,%3};"
        : "+f"(c[0]), "+f"(c[1]), "+f"(c[2]), "+f"(c[3])
        : "r"(a[0]), "r"(a[1]), "r"(a[2]), "r"(a[3]), "r"(b[0]), "r"(b[1]));
}

// ======================= split-bf16 MMA GEMM =======================
// C[M,Nn] = (Ah+Al)[M,K] @ (Bh+Bl)[Nn,K]^T   (B pre-transposed, K-major)
// EPI 0: plain fp32 C
// EPI 2: fp32 C = acc + X
// EPI 3: split-bf16 head layout [bh][s][dh] -> CH/CL
// EPI 4: split-bf16 transposed head layout [bh][dh][s] -> CH/CL
// EPI 5: fused GLU (W1 columns pre-interleaved left/right) -> split-bf16 g [M, Nn/2]
// EPI 6: merged QKV: blockIdx.z selects weight set; z<2 -> EPI3-style, z=2 -> EPI4-style
#define KC 32
#define APAD 40

template<int EPI>
__global__ __launch_bounds__(256, 2)
void mma_gemm(const __nv_bfloat16* __restrict__ Ah, const __nv_bfloat16* __restrict__ Al,
              const __nv_bfloat16* __restrict__ Bh, const __nv_bfloat16* __restrict__ Bl,
              float* __restrict__ C, const float* __restrict__ X,
              __nv_bfloat16* __restrict__ CH, __nv_bfloat16* __restrict__ CL,
              const __nv_bfloat16* Bh2, const __nv_bfloat16* Bl2,
              const __nv_bfloat16* Bh3, const __nv_bfloat16* Bl3,
              __nv_bfloat16* CH2, __nv_bfloat16* CL2,
              __nv_bfloat16* CH3, __nv_bfloat16* CL3,
              int Nn, int K) {
    __shared__ __align__(16) __nv_bfloat16 S[4][128][APAD];   // Ah, Al, Bh, Bl tiles

    const int tid  = threadIdx.x;
    const int wid  = tid >> 5, lane = tid & 31;
    const int wm   = wid & 1, wn = wid >> 1;       // warp grid 2(m) x 4(n)
    const int m0   = blockIdx.y << 7, n0 = blockIdx.x << 7;

    const __nv_bfloat16* Bh_ = Bh;
    const __nv_bfloat16* Bl_ = Bl;
    __nv_bfloat16* CH_ = CH;
    __nv_bfloat16* CL_ = CL;
    int zsel = 0;
    if (EPI == 6){
        zsel = blockIdx.z;
        if (zsel == 1){ Bh_ = Bh2; Bl_ = Bl2; CH_ = CH2; CL_ = CL2; }
        else if (zsel == 2){ Bh_ = Bh3; Bl_ = Bl3; CH_ = CH3; CL_ = CL3; }
    }

    const int r_a  = tid >> 1;
    const int c8a  = (tid & 1) << 4;

    float acc[4][4][4];
    #pragma unroll
    for (int mt = 0; mt < 4; mt++)
        #pragma unroll
        for (int nt = 0; nt < 4; nt++)
            #pragma unroll
            for (int j = 0; j < 4; j++) acc[mt][nt][j] = 0.f;

    const int nc = K / KC;
    uint4 sAh[2], sAl[2], sBh[2], sBl[2];

    {
        const __nv_bfloat16* pAh = Ah  + (size_t)(m0 + r_a) * K + c8a;
        const __nv_bfloat16* pAl = Al  + (size_t)(m0 + r_a) * K + c8a;
        const __nv_bfloat16* pBh = Bh_ + (size_t)(n0 + r_a) * K + c8a;
        const __nv_bfloat16* pBl = Bl_ + (size_t)(n0 + r_a) * K + c8a;
        sAh[0] = *(const uint4*)(pAh);     sAh[1] = *(const uint4*)(pAh + 8);
        sAl[0] = *(const uint4*)(pAl);     sAl[1] = *(const uint4*)(pAl + 8);
        sBh[0] = *(const uint4*)(pBh);     sBh[1] = *(const uint4*)(pBh + 8);
        sBl[0] = *(const uint4*)(pBl);     sBl[1] = *(const uint4*)(pBl + 8);
    }

    for (int kc = 0; kc < nc; kc++){
        __syncthreads();
        *(uint4*)&S[0][r_a][c8a]     = sAh[0];  *(uint4*)&S[0][r_a][c8a + 8] = sAh[1];
        *(uint4*)&S[1][r_a][c8a]     = sAl[0];  *(uint4*)&S[1][r_a][c8a + 8] = sAl[1];
        *(uint4*)&S[2][r_a][c8a]     = sBh[0];  *(uint4*)&S[2][r_a][c8a + 8] = sBh[1];
        *(uint4*)&S[3][r_a][c8a]     = sBl[0];  *(uint4*)&S[3][r_a][c8a + 8] = sBl[1];
        __syncthreads();

        if (kc + 1 < nc){
            const int k0 = (kc + 1) * KC;
            const __nv_bfloat16* pAh = Ah  + (size_t)(m0 + r_a) * K + k0 + c8a;
            const __nv_bfloat16* pAl = Al  + (size_t)(m0 + r_a) * K + k0 + c8a;
            const __nv_bfloat16* pBh = Bh_ + (size_t)(n0 + r_a) * K + k0 + c8a;
            const __nv_bfloat16* pBl = Bl_ + (size_t)(n0 + r_a) * K + k0 + c8a;
            sAh[0] = *(const uint4*)(pAh); sAh[1] = *(const uint4*)(pAh + 8);
            sAl[0] = *(const uint4*)(pAl); sAl[1] = *(const uint4*)(pAl + 8);
            sBh[0] = *(const uint4*)(pBh); sBh[1] = *(const uint4*)(pBh + 8);
            sBl[0] = *(const uint4*)(pBl); sBl[1] = *(const uint4*)(pBl + 8);
        }

        #pragma unroll
        for (int ks = 0; ks < 2; ks++){
            const int kb  = ks * 16 + ((lane & 3) << 1);
            const int rq  = lane >> 2;
            uint32_t bh[4][2], bl[4][2];
            #pragma unroll
            for (int nt = 0; nt < 4; nt++){
                const int n = (wn << 5) + (nt << 3) + rq;
                bh[nt][0] = *(const uint32_t*)&S[2][n][kb];
                bh[nt][1] = *(const uint32_t*)&S[2][n][kb + 8];
                bl[nt][0] = *(const uint32_t*)&S[3][n][kb];
                bl[nt][1] = *(const uint32_t*)&S[3][n][kb + 8];
            }
            #pragma unroll
            for (int mt = 0; mt < 4; mt++){
                const int r = (wm << 6) + (mt << 4) + rq;
                uint32_t ah[4], al[4];
                ah[0] = *(const uint32_t*)&S[0][r][kb];
                ah[1] = *(const uint32_t*)&S[0][r + 8][kb];
                ah[2] = *(const uint32_t*)&S[0][r][kb + 8];
                ah[3] = *(const uint32_t*)&S[0][r + 8][kb + 8];
                al[0] = *(const uint32_t*)&S[1][r][kb];
                al[1] = *(const uint32_t*)&S[1][r + 8][kb];
                al[2] = *(const uint32_t*)&S[1][r][kb + 8];
                al[3] = *(const uint32_t*)&S[1][r + 8][kb + 8];
                #pragma unroll
                for (int nt = 0; nt < 4; nt++){
                    mma16816(acc[mt][nt], ah, bh[nt]);   // Ah*Bh
                    mma16816(acc[mt][nt], al, bh[nt]);   // Al*Bh
                    mma16816(acc[mt][nt], ah, bl[nt]);   // Ah*Bl
                }
            }
        }
    }

    const int rq = lane >> 2, cg = (lane & 3) << 1;

    if (EPI == 5){
        // fused GLU: fragment pair (n, n+1) = (left, right) thanks to the
        // interleaved W1 layout. Stage outputs in smem for coalesced writes.
        __syncthreads();   // mainloop smem reads complete everywhere
        __nv_bfloat16* stage = &S[0][0][0];   // 20480 elems >= 2*8192
        #pragma unroll
        for (int mt = 0; mt < 4; mt++){
            #pragma unroll
            for (int nt = 0; nt < 4; nt++){
                const int mR = (wm << 6) + (mt << 4) + rq;
                const int cl = ((wn << 5) + (nt << 3) + cg) >> 1;
                const float g0 = acc[mt][nt][0] / (1.f + __expf(-acc[mt][nt][1]));
                const float g1 = acc[mt][nt][2] / (1.f + __expf(-acc[mt][nt][3]));
                __nv_bfloat16 h_, l_;
                bf16split(g0, h_, l_);
                stage[mR * 64 + cl] = h_;  stage[8192 + mR * 64 + cl] = l_;
                bf16split(g1, h_, l_);
                stage[(mR + 8) * 64 + cl] = h_;  stage[8192 + (mR + 8) * 64 + cl] = l_;
            }
        }
        __syncthreads();
        const int cb = n0 >> 1;                // 64 output cols per CTA
        for (int i = tid; i < 1024; i += 256){ // 128 rows x 8 uint4 segs
            const int row = i >> 3, sg = (i & 7) << 3;
            *(uint4*)(CH_ + (size_t)(m0 + row) * (2 * DD) + cb + sg) = *(uint4*)&stage[row * 64 + sg];
            *(uint4*)(CL_ + (size_t)(m0 + row) * (2 * DD) + cb + sg) = *(uint4*)&stage[8192 + row * 64 + sg];
        }
        return;
    }

    #pragma unroll
    for (int mt = 0; mt < 4; mt++){
        #pragma unroll
        for (int nt = 0; nt < 4; nt++){
            const int m = m0 + (wm << 6) + (mt << 4) + rq;
            const int n = n0 + (wn << 5) + (nt << 3) + cg;
            float2 d01 = make_float2(acc[mt][nt][0], acc[mt][nt][1]);
            float2 d23 = make_float2(acc[mt][nt][2], acc[mt][nt][3]);
            if (EPI == 3 || (EPI == 6 && zsel < 2)){
                const int bb2 = m >> 11, srow = m & 2047, hh2 = n >> 6, dh = n & 63;
                const size_t base = ((size_t)(bb2 * HH + hh2) * SS + srow) * DHH + dh;
                uint32_t h0, l0, h1, l1;
                split2(d01.x, d01.y, h0, l0);
                split2(d23.x, d23.y, h1, l1);
                *(uint32_t*)(CH_ + base)            = h0;
                *(uint32_t*)(CL_ + base)            = l0;
                *(uint32_t*)(CH_ + base + 8 * DHH)  = h1;
                *(uint32_t*)(CL_ + base + 8 * DHH)  = l1;
            } else if (EPI == 4 || (EPI == 6 && zsel == 2)){
                const int bb2 = m >> 11, srow = m & 2047, hh2 = n >> 6, dh = n & 63;
                const size_t base = ((size_t)(bb2 * HH + hh2) * DHH + dh) * SS + srow;
                __nv_bfloat16 hq, lq;
                bf16split(d01.x, hq, lq); CH_[base]          = hq; CL_[base]          = lq;
                bf16split(d01.y, hq, lq); CH_[base + SS]     = hq; CL_[base + SS]     = lq;
                bf16split(d23.x, hq, lq); CH_[base + 8]      = hq; CL_[base + 8]      = lq;
                bf16split(d23.y, hq, lq); CH_[base + SS + 8] = hq; CL_[base + SS + 8] = lq;
            } else {
                const size_t off0 = (size_t)m * Nn + n;
                const size_t off1 = (size_t)(m + 8) * Nn + n;
                if (EPI == 2){
                    float2 x0 = *(const float2*)(X + off0);
                    float2 x1 = *(const float2*)(X + off1);
                    d01.x += x0.x; d01.y += x0.y;
                    d23.x += x1.x; d23.y += x1.y;
                }
                *(float2*)(C + off0) = d01;
                *(float2*)(C + off1) = d23;
            }
        }
    }
}

// ======================= weight transpose + split =======================
// W [K,N] fp32 row-major -> Th,Tl [N,K] bf16 row-major.
// PERM=1 (W1): interleave output rows so GLU left/right pairs are adjacent:
//   src col j<2048 -> dest 2j ; j>=2048 -> dest 2(j-2048)+1
template<int PERM>
__global__ void wt_kernel(const float* __restrict__ W,
                          __nv_bfloat16* __restrict__ Th, __nv_bfloat16* __restrict__ Tl,
                          int K, int N) {
    __shared__ float t[32][33];
    const int n0 = blockIdx.x * 32, k0 = blockIdx.y * 32;
    const int tx = threadIdx.x & 31, ty = threadIdx.x >> 5;
    #pragma unroll
    for (int i = 0; i < 32; i += 8)
        t[ty + i][tx] = W[(size_t)(k0 + ty + i) * N + n0 + tx];
    __syncthreads();
    #pragma unroll
    for (int i = 0; i < 32; i += 8){
        const float v = t[tx][ty + i];
        __nv_bfloat16 h, l;
        bf16split(v, h, l);
        const int j = n0 + ty + i;
        const int jp = PERM ? ((j < 2 * DD) ? (j << 1) : (((j - 2 * DD) << 1) + 1)) : j;
        const size_t o = (size_t)jp * K + k0 + tx;
        Th[o] = h; Tl[o] = l;
    }
}

// batched transpose for the four 1024x1024 weights (one launch)
__global__ void wt4_kernel(const float* __restrict__ Wq, const float* __restrict__ Wk,
                           const float* __restrict__ Wv, const float* __restrict__ Wo,
                           __nv_bfloat16* qh, __nv_bfloat16* ql,
                           __nv_bfloat16* kh, __nv_bfloat16* kl,
                           __nv_bfloat16* vh, __nv_bfloat16* vl,
                           __nv_bfloat16* oh, __nv_bfloat16* ol) {
    __shared__ float t[32][33];
    const float* W; __nv_bfloat16 *Th, *Tl;
    switch (blockIdx.z) {
        case 0:  W = Wq; Th = qh; Tl = ql; break;
        case 1:  W = Wk; Th = kh; Tl = kl; break;
        case 2:  W = Wv; Th = vh; Tl = vl; break;
        default: W = Wo; Th = oh; Tl = ol; break;
    }
    const int n0 = blockIdx.x * 32, k0 = blockIdx.y * 32;
    const int tx = threadIdx.x & 31, ty = threadIdx.x >> 5;
    #pragma unroll
    for (int i = 0; i < 32; i += 8)
        t[ty + i][tx] = W[(size_t)(k0 + ty + i) * DD + n0 + tx];
    __syncthreads();
    #pragma unroll
    for (int i = 0; i < 32; i += 8){
        const float v = t[tx][ty + i];
        __nv_bfloat16 h, l;
        bf16split(v, h, l);
        const size_t o = (size_t)(n0 + ty + i) * DD + k0 + tx;
        Th[o] = h; Tl[o] = l;
    }
}

// ======================= LayerNorm -> split bf16 =======================
__global__ void ln_bf16_kernel(const float* __restrict__ x,
                               const float* __restrict__ gamma,
                               const float* __restrict__ beta,
                               __nv_bfloat16* __restrict__ yh,
                               __nv_bfloat16* __restrict__ yl) {
    const int row = blockIdx.x;
    const int tid = threadIdx.x;
    const float* xr = x + (size_t)row * DD;
    float4 v = *(const float4*)(xr + tid * 4);
    float s  = v.x + v.y + v.z + v.w;
    float ss = v.x*v.x + v.y*v.y + v.z*v.z + v.w*v.w;
    #pragma unroll
    for (int off = 16; off; off >>= 1) {
        s  += __shfl_xor_sync(0xffffffffu, s,  off);
        ss += __shfl_xor_sync(0xffffffffu, ss, off);
    }
    __shared__ float sh[8], sh2[8];
    if ((tid & 31) == 0) { sh[tid >> 5] = s; sh2[tid >> 5] = ss; }
    __syncthreads();
    float tot = 0.f, tot2 = 0.f;
    #pragma unroll
    for (int i = 0; i < 8; i++) { tot += sh[i]; tot2 += sh2[i]; }
    const float mean = tot * (1.f / DD);
    const float var  = tot2 * (1.f / DD) - mean * mean;
    const float inv  = rsqrtf(var + EPSF);
    float4 g = *(const float4*)(gamma + tid * 4);
    float4 b = *(const float4*)(beta  + tid * 4);
    float o0 = g.x * (v.x - mean) * inv + b.x;
    float o1 = g.y * (v.y - mean) * inv + b.y;
    float o2 = g.z * (v.z - mean) * inv + b.z;
    float o3 = g.w * (v.w - mean) * inv + b.w;
    uint32_t h0, l0, h1, l1;
    split2(o0, o1, h0, l0);
    split2(o2, o3, h1, l1);
    uint2 ph = make_uint2(h0, h1), pl = make_uint2(l0, l1);
    *(uint2*)(yh + (size_t)row * DD + tid * 4) = ph;
    *(uint2*)(yl + (size_t)row * DD + tid * 4) = pl;
}

// ======================= tensor-core flash attention =======================
// 128 threads / 4 warps, 64-query tile. Split-bf16 3-pass for both QK and PV.
// Q/K global: [bh][s][dh] split bf16.  V global: [bh][dh][s] split bf16 (transposed).
#define DP 72
#define ATT2_SMEM (6 * 64 * DP * 2)

__global__ __launch_bounds__(128)
void attn_mma(const __nv_bfloat16* __restrict__ Qh_, const __nv_bfloat16* __restrict__ Ql_,
              const __nv_bfloat16* __restrict__ Kh_, const __nv_bfloat16* __restrict__ Kl_,
              const __nv_bfloat16* __restrict__ Vth_, const __nv_bfloat16* __restrict__ Vtl_,
              const int* __restrict__ amask,
              __nv_bfloat16* __restrict__ Oh, __nv_bfloat16* __restrict__ Ol) {
    extern __shared__ __align__(16) __nv_bfloat16 smx[];
    __nv_bfloat16* Qsh = smx;
    __nv_bfloat16* Qsl = Qsh + 64 * DP;
    __nv_bfloat16* Ksh = Qsl + 64 * DP;
    __nv_bfloat16* Ksl = Ksh + 64 * DP;
    __nv_bfloat16* Vsh = Ksl + 64 * DP;   // [dh][key]
    __nv_bfloat16* Vsl = Vsh + 64 * DP;
    __shared__ int mk[64];

    const int qb = blockIdx.x, bh = blockIdx.y, b = bh >> 4, h = bh & 15;
    const int tid = threadIdx.x, lane = tid & 31, w = tid >> 5;
    const int rq = lane >> 2, t2 = (lane & 3) << 1;

    // stage Q tile once
    {
        const __nv_bfloat16* gh = Qh_ + ((size_t)bh * SS + qb * 64) * DHH;
        const __nv_bfloat16* gl = Ql_ + ((size_t)bh * SS + qb * 64) * DHH;
        for (int idx = tid; idx < 64 * 8; idx += 128) {
            const int r = idx >> 3, sg = (idx & 7) << 3;
            *(uint4*)&Qsh[r * DP + sg] = *(const uint4*)(gh + r * DHH + sg);
            *(uint4*)&Qsl[r * DP + sg] = *(const uint4*)(gl + r * DHH + sg);
        }
    }

    float o[8][4];
    #pragma unroll
    for (int i = 0; i < 8; i++) { o[i][0] = o[i][1] = o[i][2] = o[i][3] = 0.f; }
    float m0 = -1e30f, m1 = -1e30f, l0 = 0.f, l1 = 0.f;
    const int rg0 = qb * 64 + (w << 4) + rq;   // global query row (first of pair)

    for (int kb = 0; kb <= qb; kb++) {
        __syncthreads();
        {
            const __nv_bfloat16* gh = Kh_  + ((size_t)bh * SS + kb * 64) * DHH;
            const __nv_bfloat16* gl = Kl_  + ((size_t)bh * SS + kb * 64) * DHH;
            const __nv_bfloat16* vh = Vth_ + ((size_t)bh * DHH) * SS + kb * 64;
            const __nv_bfloat16* vl = Vtl_ + ((size_t)bh * DHH) * SS + kb * 64;
            for (int idx = tid; idx < 64 * 8; idx += 128) {
                const int r = idx >> 3, sg = (idx & 7) << 3;
                *(uint4*)&Ksh[r * DP + sg] = *(const uint4*)(gh + r * DHH + sg);
                *(uint4*)&Ksl[r * DP + sg] = *(const uint4*)(gl + r * DHH + sg);
                *(uint4*)&Vsh[r * DP + sg] = *(const uint4*)(vh + (size_t)r * SS + sg);
                *(uint4*)&Vsl[r * DP + sg] = *(const uint4*)(vl + (size_t)r * SS + sg);
            }
            if (tid < 64) mk[tid] = amask[b * SS + kb * 64 + tid];
        }
        __syncthreads();

        // S = (Qh+Ql) @ (Kh+Kl)^T  (3-pass)
        float s[8][4];
        #pragma unroll
        for (int i = 0; i < 8; i++) { s[i][0] = s[i][1] = s[i][2] = s[i][3] = 0.f; }
        #pragma unroll
        for (int k16 = 0; k16 < 4; k16++) {
            const int ar = (w << 4) + rq;
            const int ac = t2 + (k16 << 4);
            uint32_t ah4[4], al4[4];
            ah4[0] = *(const uint32_t*)&Qsh[ar * DP + ac];
            ah4[1] = *(const uint32_t*)&Qsh[(ar + 8) * DP + ac];
            ah4[2] = *(const uint32_t*)&Qsh[ar * DP + ac + 8];
            ah4[3] = *(const uint32_t*)&Qsh[(ar + 8) * DP + ac + 8];
            al4[0] = *(const uint32_t*)&Qsl[ar * DP + ac];
            al4[1] = *(const uint32_t*)&Qsl[(ar + 8) * DP + ac];
            al4[2] = *(const uint32_t*)&Qsl[ar * DP + ac + 8];
            al4[3] = *(const uint32_t*)&Qsl[(ar + 8) * DP + ac + 8];
            #pragma unroll
            for (int n8 = 0; n8 < 8; n8++) {
                const int br = (n8 << 3) + rq;
                uint32_t bh2[2], bl2[2];
                bh2[0] = *(const uint32_t*)&Ksh[br * DP + ac];
                bh2[1] = *(const uint32_t*)&Ksh[br * DP + ac + 8];
                bl2[0] = *(const uint32_t*)&Ksl[br * DP + ac];
                bl2[1] = *(const uint32_t*)&Ksl[br * DP + ac + 8];
                mma16816(s[n8], ah4, bh2);
                mma16816(s[n8], al4, bh2);
                mma16816(s[n8], ah4, bl2);
            }
        }

        // scale + mask + online softmax (rows r and r+8)
        const bool diag = (kb == qb);
        float rm0 = -1e30f, rm1 = -1e30f;
        #pragma unroll
        for (int n8 = 0; n8 < 8; n8++) {
            const int c0 = (n8 << 3) + t2;
            #pragma unroll
            for (int v = 0; v < 2; v++) {
                const int c = c0 + v;
                const int cgl = kb * 64 + c;
                float x0 = s[n8][v] * 0.125f;
                float x1 = s[n8][2 + v] * 0.125f;
                const bool km = (mk[c] != 0);
                if (!km || (diag && cgl > rg0))     x0 = -1e30f;
                if (!km || (diag && cgl > rg0 + 8)) x1 = -1e30f;
                s[n8][v] = x0; s[n8][2 + v] = x1;
                rm0 = fmaxf(rm0, x0); rm1 = fmaxf(rm1, x1);
            }
        }
        rm0 = fmaxf(rm0, __shfl_xor_sync(0xffffffffu, rm0, 1));
        rm0 = fmaxf(rm0, __shfl_xor_sync(0xffffffffu, rm0, 2));
        rm1 = fmaxf(rm1, __shfl_xor_sync(0xffffffffu, rm1, 1));
        rm1 = fmaxf(rm1, __shfl_xor_sync(0xffffffffu, rm1, 2));
        const float mn0 = fmaxf(m0, rm0), mn1 = fmaxf(m1, rm1);
        const float a0 = __expf(m0 - mn0), a1 = __expf(m1 - mn1);
        float rs0 = 0.f, rs1 = 0.f;
        #pragma unroll
        for (int n8 = 0; n8 < 8; n8++) {
            #pragma unroll
            for (int v = 0; v < 2; v++) {
                float p0 = __expf(s[n8][v] - mn0);
                float p1 = __expf(s[n8][2 + v] - mn1);
                s[n8][v] = p0; s[n8][2 + v] = p1;
                rs0 += p0; rs1 += p1;
            }
        }
        rs0 += __shfl_xor_sync(0xffffffffu, rs0, 1);
        rs0 += __shfl_xor_sync(0xffffffffu, rs0, 2);
        rs1 += __shfl_xor_sync(0xffffffffu, rs1, 1);
        rs1 += __shfl_xor_sync(0xffffffffu, rs1, 2);
        l0 = l0 * a0 + rs0; l1 = l1 * a1 + rs1;
        m0 = mn0; m1 = mn1;
        #pragma unroll
        for (int n8 = 0; n8 < 8; n8++) {
            o[n8][0] *= a0; o[n8][1] *= a0; o[n8][2] *= a1; o[n8][3] *= a1;
        }

        // repack P (C layout) -> A fragments (split bf16), in registers
        uint32_t Ph[4][4], Pl[4][4];
        #pragma unroll
        for (int jj = 0; jj < 4; jj++) {
            const int j0 = jj << 1, j1 = j0 + 1;
            split2(s[j0][0], s[j0][1], Ph[jj][0], Pl[jj][0]);
            split2(s[j0][2], s[j0][3], Ph[jj][1], Pl[jj][1]);
            split2(s[j1][0], s[j1][1], Ph[jj][2], Pl[jj][2]);
            split2(s[j1][2], s[j1][3], Ph[jj][3], Pl[jj][3]);
        }

        // O += (Ph+Pl) @ (Vh+Vl)   (V stored [dh][key] = B operand col-major)
        #pragma unroll
        for (int jj = 0; jj < 4; jj++) {
            const int kc = t2 + (jj << 4);
            #pragma unroll
            for (int n8 = 0; n8 < 8; n8++) {
                const int vr = (n8 << 3) + rq;
                uint32_t vh2[2], vl2[2];
                vh2[0] = *(const uint32_t*)&Vsh[vr * DP + kc];
                vh2[1] = *(const uint32_t*)&Vsh[vr * DP + kc + 8];
                vl2[0] = *(const uint32_t*)&Vsl[vr * DP + kc];
                vl2[1] = *(const uint32_t*)&Vsl[vr * DP + kc + 8];
                mma16816(o[n8], Ph[jj], vh2);
                mma16816(o[n8], Pl[jj], vh2);
                mma16816(o[n8], Ph[jj], vl2);
            }
        }
    }

    // finalize -> split bf16 [B,S,D]
    const float i0 = 1.f / l0, i1 = 1.f / l1;
    const size_t row0 = (size_t)(b * SS) + qb * 64 + (w << 4) + rq;
    #pragma unroll
    for (int n8 = 0; n8 < 8; n8++) {
        const int col = h * DHH + (n8 << 3) + t2;
        uint32_t hh0, ll0, hh1, ll1;
        split2(o[n8][0] * i0, o[n8][1] * i0, hh0, ll0);
        split2(o[n8][2] * i1, o[n8][3] * i1, hh1, ll1);
        *(uint32_t*)(Oh + row0 * DD + col)       = hh0;
        *(uint32_t*)(Ol + row0 * DD + col)       = ll0;
        *(uint32_t*)(Oh + (row0 + 8) * DD + col) = hh1;
        *(uint32_t*)(Ol + (row0 + 8) * DD + col) = ll1;
    }
}

// ======================= host launcher =======================
extern "C" void kernel_launch(void* const* d_in, const int* in_sizes, int n_in,
                              void* d_out, int out_size) {
    const float* x      = (const float*)d_in[0];
    const int*   amask  = (const int*)  d_in[1];
    const float* Wq     = (const float*)d_in[2];
    const float* Wk     = (const float*)d_in[3];
    const float* Wv     = (const float*)d_in[4];
    const float* Wo     = (const float*)d_in[5];
    const float* W1     = (const float*)d_in[6];
    const float* W2     = (const float*)d_in[7];
    const float* gamma1 = (const float*)d_in[8];
    const float* beta1  = (const float*)d_in[9];
    const float* gamma2 = (const float*)d_in[10];
    const float* beta2  = (const float*)d_in[11];
    float* out = (float*)d_out;

    float *p_x1;
    __nv_bfloat16 *p_a1h, *p_a1l, *p_ath, *p_atl, *p_l2h, *p_l2l, *p_gh, *p_gl;
    __nv_bfloat16 *p_qh, *p_ql, *p_kh, *p_kl, *p_vth, *p_vtl;
    __nv_bfloat16 *p_wqh, *p_wql, *p_wkh, *p_wkl, *p_wvh, *p_wvl, *p_woh, *p_wol;
    __nv_bfloat16 *p_w1h, *p_w1l, *p_w2h, *p_w2l;
    cudaGetSymbolAddress((void**)&p_x1,  g_x1);
    cudaGetSymbolAddress((void**)&p_a1h, g_a1h); cudaGetSymbolAddress((void**)&p_a1l, g_a1l);
    cudaGetSymbolAddress((void**)&p_ath, g_ath); cudaGetSymbolAddress((void**)&p_atl, g_atl);
    cudaGetSymbolAddress((void**)&p_l2h, g_l2h); cudaGetSymbolAddress((void**)&p_l2l, g_l2l);
    cudaGetSymbolAddress((void**)&p_gh,  g_gh);  cudaGetSymbolAddress((void**)&p_gl,  g_gl);
    cudaGetSymbolAddress((void**)&p_qh,  g_qh);  cudaGetSymbolAddress((void**)&p_ql,  g_ql);
    cudaGetSymbolAddress((void**)&p_kh,  g_kh);  cudaGetSymbolAddress((void**)&p_kl,  g_kl);
    cudaGetSymbolAddress((void**)&p_vth, g_vth); cudaGetSymbolAddress((void**)&p_vtl, g_vtl);
    cudaGetSymbolAddress((void**)&p_wqh, g_wqh); cudaGetSymbolAddress((void**)&p_wql, g_wql);
    cudaGetSymbolAddress((void**)&p_wkh, g_wkh); cudaGetSymbolAddress((void**)&p_wkl, g_wkl);
    cudaGetSymbolAddress((void**)&p_wvh, g_wvh); cudaGetSymbolAddress((void**)&p_wvl, g_wvl);
    cudaGetSymbolAddress((void**)&p_woh, g_woh); cudaGetSymbolAddress((void**)&p_wol, g_wol);
    cudaGetSymbolAddress((void**)&p_w1h, g_w1h); cudaGetSymbolAddress((void**)&p_w1l, g_w1l);
    cudaGetSymbolAddress((void**)&p_w2h, g_w2h); cudaGetSymbolAddress((void**)&p_w2l, g_w2l);

    cudaFuncSetAttribute(attn_mma, cudaFuncAttributeMaxDynamicSharedMemorySize, ATT2_SMEM);

    // 0. weight transpose + split (Q/K/V/Wo batched; W1 interleaved for fused GLU)
    wt4_kernel<<<dim3(DD/32, DD/32, 4), 256>>>(Wq, Wk, Wv, Wo,
                                               p_wqh, p_wql, p_wkh, p_wkl,
                                               p_wvh, p_wvl, p_woh, p_wol);
    wt_kernel<1><<<dim3(4*DD/32, DD/32),   256>>>(W1, p_w1h, p_w1l, DD,   4*DD);
    wt_kernel<0><<<dim3(DD/32,   2*DD/32), 256>>>(W2, p_w2h, p_w2l, 2*DD, DD);

    // 1. ln1 -> split bf16
    ln_bf16_kernel<<<ROWS, 256>>>(x, gamma1, beta1, p_a1h, p_a1l);
    // 2. merged QKV projection (z selects weight/output; Q,K head layout; V transposed)
    mma_gemm<6><<<dim3(8, 32, 3), 256>>>(p_a1h, p_a1l, p_wqh, p_wql,
                                         nullptr, nullptr, p_qh, p_ql,
                                         p_wkh, p_wkl, p_wvh, p_wvl,
                                         p_kh, p_kl, p_vth, p_vtl, DD, DD);
    // 3. tensor-core causal flash attention -> split bf16 [B,S,D]
    attn_mma<<<dim3(SS/64, BB*HH), 128, ATT2_SMEM>>>(p_qh, p_ql, p_kh, p_kl, p_vth, p_vtl,
                                                     amask, p_ath, p_atl);
    // 4. Wo + residual -> x1
    mma_gemm<2><<<dim3(8, 32), 256>>>(p_ath, p_atl, p_woh, p_wol, p_x1, x, nullptr, nullptr,
                                      nullptr, nullptr, nullptr, nullptr,
                                      nullptr, nullptr, nullptr, nullptr, DD, DD);
    // 5. ln2 -> split bf16
    ln_bf16_kernel<<<ROWS, 256>>>(p_x1, gamma2, beta2, p_l2h, p_l2l);
    // 6. W1 (D -> 4D, interleaved) with fused GLU -> split-bf16 g
    mma_gemm<5><<<dim3(32, 32), 256>>>(p_l2h, p_l2l, p_w1h, p_w1l, nullptr, nullptr, p_gh, p_gl,
                                       nullptr, nullptr, nullptr, nullptr,
                                       nullptr, nullptr, nullptr, nullptr, 4*DD, DD);
    // 7. W2 + residual -> out
    mma_gemm<2><<<dim3(8, 32), 256>>>(p_gh, p_gl, p_w2h, p_w2l, out, p_x1, nullptr, nullptr,
                                      nullptr, nullptr, nullptr, nullptr,
                                      nullptr, nullptr, nullptr, nullptr, DD, 2*DD);
}

// round 15
// speedup vs baseline: 1.1468x; 1.1468x over previous
#include <cuda_runtime.h>
#include <cuda_bf16.h>
#include <cstdint>
#include <math.h>

// Problem constants
#define BB 2
#define SS 2048
#define DD 1024
#define HH 16
#define DHH 64
#define ROWS (BB*SS)        // 4096
#define EPSF 1e-5f

// ======================= scratch (device globals) =======================
__device__ float g_x1  [(size_t)ROWS*DD];

// split-bf16 activations (hi/lo)
__device__ __nv_bfloat16 g_a1h[(size_t)ROWS*DD],   g_a1l[(size_t)ROWS*DD];
__device__ __nv_bfloat16 g_ath[(size_t)ROWS*DD],   g_atl[(size_t)ROWS*DD];
__device__ __nv_bfloat16 g_l2h[(size_t)ROWS*DD],   g_l2l[(size_t)ROWS*DD];
__device__ __nv_bfloat16 g_gh [(size_t)ROWS*2*DD], g_gl [(size_t)ROWS*2*DD];

// split-bf16 Q/K head-layout [bh][s][dh], V transposed [bh][dh][s]
__device__ __nv_bfloat16 g_qh [(size_t)ROWS*DD], g_ql [(size_t)ROWS*DD];
__device__ __nv_bfloat16 g_kh [(size_t)ROWS*DD], g_kl [(size_t)ROWS*DD];
__device__ __nv_bfloat16 g_vth[(size_t)ROWS*DD], g_vtl[(size_t)ROWS*DD];

// transposed split-bf16 weights: [N, K] K-major
__device__ __nv_bfloat16 g_wqh[(size_t)DD*DD], g_wql[(size_t)DD*DD];
__device__ __nv_bfloat16 g_wkh[(size_t)DD*DD], g_wkl[(size_t)DD*DD];
__device__ __nv_bfloat16 g_wvh[(size_t)DD*DD], g_wvl[(size_t)DD*DD];
__device__ __nv_bfloat16 g_woh[(size_t)DD*DD], g_wol[(size_t)DD*DD];
__device__ __nv_bfloat16 g_w1h[(size_t)DD*4*DD], g_w1l[(size_t)DD*4*DD];
__device__ __nv_bfloat16 g_w2h[(size_t)2*DD*DD], g_w2l[(size_t)2*DD*DD];

__device__ __forceinline__ void bf16split(float v, __nv_bfloat16& h, __nv_bfloat16& l){
    h = __float2bfloat16(v);
    l = __float2bfloat16(v - __bfloat162float(h));
}
// split a float pair into packed bf16x2 hi/lo words (low half = first elem)
__device__ __forceinline__ void split2(float a, float b, uint32_t& hi, uint32_t& lo){
    __nv_bfloat16 ha = __float2bfloat16(a), hb = __float2bfloat16(b);
    float ra = a - __bfloat162float(ha), rb = b - __bfloat162float(hb);
    __nv_bfloat16 la = __float2bfloat16(ra), lb = __float2bfloat16(rb);
    hi = ((uint32_t)__bfloat16_as_ushort(hb) << 16) | (uint32_t)__bfloat16_as_ushort(ha);
    lo = ((uint32_t)__bfloat16_as_ushort(lb) << 16) | (uint32_t)__bfloat16_as_ushort(la);
}

// m16n8k16 bf16 MMA, fp32 accumulate (baseline PTX, works on non-'a' targets)
__device__ __forceinline__ void mma16816(float* c, const uint32_t* a, const uint32_t* b){
    asm volatile(
        "mma.sync.aligned.m16n8k16.row.col.f32.bf16.bf16.f32 "
        "{%0,%1,%2,%3}, {%4,%5,%6,%7}, {%8,%9}, {%0,%1,%2,%3};"
        : "+f"(c[0]), "+f"(c[1]), "+f"(c[2]), "+f"(c[3])
        : "r"(a[0]), "r"(a[1]), "r"(a[2]), "r"(a[3]), "r"(b[0]), "r"(b[1]));
}

// ======================= split-bf16 MMA GEMM =======================
// C[M,Nn] = (Ah+Al)[M,K] @ (Bh+Bl)[Nn,K]^T   (B pre-transposed, K-major)
// EPI 0: plain fp32 C
// EPI 2: fp32 C = acc + X
// EPI 3: split-bf16 head layout [bh][s][dh] -> CH/CL
// EPI 4: split-bf16 transposed head layout [bh][dh][s] -> CH/CL
// EPI 5: fused GLU (W1 columns pre-interleaved left/right) -> split-bf16 g [M, Nn/2]
// EPI 6: merged QKV: blockIdx.z selects weight set; z<2 -> EPI3-style, z=2 -> EPI4-style
#define KC 32
#define APAD 40

template<int EPI>
__global__ __launch_bounds__(256)
void mma_gemm(const __nv_bfloat16* __restrict__ Ah, const __nv_bfloat16* __restrict__ Al,
              const __nv_bfloat16* __restrict__ Bh, const __nv_bfloat16* __restrict__ Bl,
              float* __restrict__ C, const float* __restrict__ X,
              __nv_bfloat16* __restrict__ CH, __nv_bfloat16* __restrict__ CL,
              const __nv_bfloat16* Bh2, const __nv_bfloat16* Bl2,
              const __nv_bfloat16* Bh3, const __nv_bfloat16* Bl3,
              __nv_bfloat16* CH2, __nv_bfloat16* CL2,
              __nv_bfloat16* CH3, __nv_bfloat16* CL3,
              int Nn, int K) {
    __shared__ __align__(16) __nv_bfloat16 S[4][128][APAD];   // Ah, Al, Bh, Bl tiles

    const int tid  = threadIdx.x;
    const int wid  = tid >> 5, lane = tid & 31;
    const int wm   = wid & 1, wn = wid >> 1;       // warp grid 2(m) x 4(n)
    const int m0   = blockIdx.y << 7, n0 = blockIdx.x << 7;

    const __nv_bfloat16* Bh_ = Bh;
    const __nv_bfloat16* Bl_ = Bl;
    __nv_bfloat16* CH_ = CH;
    __nv_bfloat16* CL_ = CL;
    int zsel = 0;
    if (EPI == 6){
        zsel = blockIdx.z;
        if (zsel == 1){ Bh_ = Bh2; Bl_ = Bl2; CH_ = CH2; CL_ = CL2; }
        else if (zsel == 2){ Bh_ = Bh3; Bl_ = Bl3; CH_ = CH3; CL_ = CL3; }
    }

    const int r_a  = tid >> 1;
    const int c8a  = (tid & 1) << 4;

    float acc[4][4][4];
    #pragma unroll
    for (int mt = 0; mt < 4; mt++)
        #pragma unroll
        for (int nt = 0; nt < 4; nt++)
            #pragma unroll
            for (int j = 0; j < 4; j++) acc[mt][nt][j] = 0.f;

    const int nc = K / KC;
    uint4 sAh[2], sAl[2], sBh[2], sBl[2];

    {
        const __nv_bfloat16* pAh = Ah  + (size_t)(m0 + r_a) * K + c8a;
        const __nv_bfloat16* pAl = Al  + (size_t)(m0 + r_a) * K + c8a;
        const __nv_bfloat16* pBh = Bh_ + (size_t)(n0 + r_a) * K + c8a;
        const __nv_bfloat16* pBl = Bl_ + (size_t)(n0 + r_a) * K + c8a;
        sAh[0] = *(const uint4*)(pAh);     sAh[1] = *(const uint4*)(pAh + 8);
        sAl[0] = *(const uint4*)(pAl);     sAl[1] = *(const uint4*)(pAl + 8);
        sBh[0] = *(const uint4*)(pBh);     sBh[1] = *(const uint4*)(pBh + 8);
        sBl[0] = *(const uint4*)(pBl);     sBl[1] = *(const uint4*)(pBl + 8);
    }

    for (int kc = 0; kc < nc; kc++){
        __syncthreads();
        *(uint4*)&S[0][r_a][c8a]     = sAh[0];  *(uint4*)&S[0][r_a][c8a + 8] = sAh[1];
        *(uint4*)&S[1][r_a][c8a]     = sAl[0];  *(uint4*)&S[1][r_a][c8a + 8] = sAl[1];
        *(uint4*)&S[2][r_a][c8a]     = sBh[0];  *(uint4*)&S[2][r_a][c8a + 8] = sBh[1];
        *(uint4*)&S[3][r_a][c8a]     = sBl[0];  *(uint4*)&S[3][r_a][c8a + 8] = sBl[1];
        __syncthreads();

        if (kc + 1 < nc){
            const int k0 = (kc + 1) * KC;
            const __nv_bfloat16* pAh = Ah  + (size_t)(m0 + r_a) * K + k0 + c8a;
            const __nv_bfloat16* pAl = Al  + (size_t)(m0 + r_a) * K + k0 + c8a;
            const __nv_bfloat16* pBh = Bh_ + (size_t)(n0 + r_a) * K + k0 + c8a;
            const __nv_bfloat16* pBl = Bl_ + (size_t)(n0 + r_a) * K + k0 + c8a;
            sAh[0] = *(const uint4*)(pAh); sAh[1] = *(const uint4*)(pAh + 8);
            sAl[0] = *(const uint4*)(pAl); sAl[1] = *(const uint4*)(pAl + 8);
            sBh[0] = *(const uint4*)(pBh); sBh[1] = *(const uint4*)(pBh + 8);
            sBl[0] = *(const uint4*)(pBl); sBl[1] = *(const uint4*)(pBl + 8);
        }

        #pragma unroll
        for (int ks = 0; ks < 2; ks++){
            const int kb  = ks * 16 + ((lane & 3) << 1);
            const int rq  = lane >> 2;
            uint32_t bh[4][2], bl[4][2];
            #pragma unroll
            for (int nt = 0; nt < 4; nt++){
                const int n = (wn << 5) + (nt << 3) + rq;
                bh[nt][0] = *(const uint32_t*)&S[2][n][kb];
                bh[nt][1] = *(const uint32_t*)&S[2][n][kb + 8];
                bl[nt][0] = *(const uint32_t*)&S[3][n][kb];
                bl[nt][1] = *(const uint32_t*)&S[3][n][kb + 8];
            }
            #pragma unroll
            for (int mt = 0; mt < 4; mt++){
                const int r = (wm << 6) + (mt << 4) + rq;
                uint32_t ah[4], al[4];
                ah[0] = *(const uint32_t*)&S[0][r][kb];
                ah[1] = *(const uint32_t*)&S[0][r + 8][kb];
                ah[2] = *(const uint32_t*)&S[0][r][kb + 8];
                ah[3] = *(const uint32_t*)&S[0][r + 8][kb + 8];
                al[0] = *(const uint32_t*)&S[1][r][kb];
                al[1] = *(const uint32_t*)&S[1][r + 8][kb];
                al[2] = *(const uint32_t*)&S[1][r][kb + 8];
                al[3] = *(const uint32_t*)&S[1][r + 8][kb + 8];
                #pragma unroll
                for (int nt = 0; nt < 4; nt++){
                    mma16816(acc[mt][nt], ah, bh[nt]);   // Ah*Bh
                    mma16816(acc[mt][nt], al, bh[nt]);   // Al*Bh
                    mma16816(acc[mt][nt], ah, bl[nt]);   // Ah*Bl
                }
            }
        }
    }

    const int rq = lane >> 2, cg = (lane & 3) << 1;

    if (EPI == 5){
        // fused GLU: fragment pair (n, n+1) = (left, right) thanks to the
        // interleaved W1 layout. Stage outputs in smem for coalesced writes.
        __syncthreads();   // mainloop smem reads complete everywhere
        __nv_bfloat16* stage = &S[0][0][0];   // 20480 elems >= 2*8192
        #pragma unroll
        for (int mt = 0; mt < 4; mt++){
            #pragma unroll
            for (int nt = 0; nt < 4; nt++){
                const int mR = (wm << 6) + (mt << 4) + rq;
                const int cl = ((wn << 5) + (nt << 3) + cg) >> 1;
                const float g0 = acc[mt][nt][0] / (1.f + __expf(-acc[mt][nt][1]));
                const float g1 = acc[mt][nt][2] / (1.f + __expf(-acc[mt][nt][3]));
                __nv_bfloat16 h_, l_;
                bf16split(g0, h_, l_);
                stage[mR * 64 + cl] = h_;  stage[8192 + mR * 64 + cl] = l_;
                bf16split(g1, h_, l_);
                stage[(mR + 8) * 64 + cl] = h_;  stage[8192 + (mR + 8) * 64 + cl] = l_;
            }
        }
        __syncthreads();
        const int cb = n0 >> 1;                // 64 output cols per CTA
        for (int i = tid; i < 1024; i += 256){ // 128 rows x 8 uint4 segs
            const int row = i >> 3, sg = (i & 7) << 3;
            *(uint4*)(CH + (size_t)(m0 + row) * (2 * DD) + cb + sg) = *(uint4*)&stage[row * 64 + sg];
            *(uint4*)(CL + (size_t)(m0 + row) * (2 * DD) + cb + sg) = *(uint4*)&stage[8192 + row * 64 + sg];
        }
        return;
    }

    #pragma unroll
    for (int mt = 0; mt < 4; mt++){
        #pragma unroll
        for (int nt = 0; nt < 4; nt++){
            const int m = m0 + (wm << 6) + (mt << 4) + rq;
            const int n = n0 + (wn << 5) + (nt << 3) + cg;
            float2 d01 = make_float2(acc[mt][nt][0], acc[mt][nt][1]);
            float2 d23 = make_float2(acc[mt][nt][2], acc[mt][nt][3]);
            if (EPI == 3 || (EPI == 6 && zsel < 2)){
                const int bb2 = m >> 11, srow = m & 2047, hh2 = n >> 6, dh = n & 63;
                const size_t base = ((size_t)(bb2 * HH + hh2) * SS + srow) * DHH + dh;
                uint32_t h0, l0, h1, l1;
                split2(d01.x, d01.y, h0, l0);
                split2(d23.x, d23.y, h1, l1);
                *(uint32_t*)(CH_ + base)            = h0;
                *(uint32_t*)(CL_ + base)            = l0;
                *(uint32_t*)(CH_ + base + 8 * DHH)  = h1;
                *(uint32_t*)(CL_ + base + 8 * DHH)  = l1;
            } else if (EPI == 4 || (EPI == 6 && zsel == 2)){
                const int bb2 = m >> 11, srow = m & 2047, hh2 = n >> 6, dh = n & 63;
                const size_t base = ((size_t)(bb2 * HH + hh2) * DHH + dh) * SS + srow;
                __nv_bfloat16 hq, lq;
                bf16split(d01.x, hq, lq); CH_[base]          = hq; CL_[base]          = lq;
                bf16split(d01.y, hq, lq); CH_[base + SS]     = hq; CL_[base + SS]     = lq;
                bf16split(d23.x, hq, lq); CH_[base + 8]      = hq; CL_[base + 8]      = lq;
                bf16split(d23.y, hq, lq); CH_[base + SS + 8] = hq; CL_[base + SS + 8] = lq;
            } else {
                const size_t off0 = (size_t)m * Nn + n;
                const size_t off1 = (size_t)(m + 8) * Nn + n;
                if (EPI == 2){
                    float2 x0 = *(const float2*)(X + off0);
                    float2 x1 = *(const float2*)(X + off1);
                    d01.x += x0.x; d01.y += x0.y;
                    d23.x += x1.x; d23.y += x1.y;
                }
                *(float2*)(C + off0) = d01;
                *(float2*)(C + off1) = d23;
            }
        }
    }
}

// ======================= weight transpose + split =======================
// W [K,N] fp32 row-major -> Th,Tl [N,K] bf16 row-major.
// PERM=1 (W1): interleave output rows so GLU left/right pairs are adjacent:
//   src col j<2048 -> dest 2j ; j>=2048 -> dest 2(j-2048)+1
template<int PERM>
__global__ void wt_kernel(const float* __restrict__ W,
                          __nv_bfloat16* __restrict__ Th, __nv_bfloat16* __restrict__ Tl,
                          int K, int N) {
    __shared__ float t[32][33];
    const int n0 = blockIdx.x * 32, k0 = blockIdx.y * 32;
    const int tx = threadIdx.x & 31, ty = threadIdx.x >> 5;
    #pragma unroll
    for (int i = 0; i < 32; i += 8)
        t[ty + i][tx] = W[(size_t)(k0 + ty + i) * N + n0 + tx];
    __syncthreads();
    #pragma unroll
    for (int i = 0; i < 32; i += 8){
        const float v = t[tx][ty + i];
        __nv_bfloat16 h, l;
        bf16split(v, h, l);
        const int j = n0 + ty + i;
        const int jp = PERM ? ((j < 2 * DD) ? (j << 1) : (((j - 2 * DD) << 1) + 1)) : j;
        const size_t o = (size_t)jp * K + k0 + tx;
        Th[o] = h; Tl[o] = l;
    }
}

// batched transpose for the four 1024x1024 weights (one launch)
__global__ void wt4_kernel(const float* __restrict__ Wq, const float* __restrict__ Wk,
                           const float* __restrict__ Wv, const float* __restrict__ Wo,
                           __nv_bfloat16* qh, __nv_bfloat16* ql,
                           __nv_bfloat16* kh, __nv_bfloat16* kl,
                           __nv_bfloat16* vh, __nv_bfloat16* vl,
                           __nv_bfloat16* oh, __nv_bfloat16* ol) {
    __shared__ float t[32][33];
    const float* W; __nv_bfloat16 *Th, *Tl;
    switch (blockIdx.z) {
        case 0:  W = Wq; Th = qh; Tl = ql; break;
        case 1:  W = Wk; Th = kh; Tl = kl; break;
        case 2:  W = Wv; Th = vh; Tl = vl; break;
        default: W = Wo; Th = oh; Tl = ol; break;
    }
    const int n0 = blockIdx.x * 32, k0 = blockIdx.y * 32;
    const int tx = threadIdx.x & 31, ty = threadIdx.x >> 5;
    #pragma unroll
    for (int i = 0; i < 32; i += 8)
        t[ty + i][tx] = W[(size_t)(k0 + ty + i) * DD + n0 + tx];
    __syncthreads();
    #pragma unroll
    for (int i = 0; i < 32; i += 8){
        const float v = t[tx][ty + i];
        __nv_bfloat16 h, l;
        bf16split(v, h, l);
        const size_t o = (size_t)(n0 + ty + i) * DD + k0 + tx;
        Th[o] = h; Tl[o] = l;
    }
}

// ======================= LayerNorm -> split bf16 =======================
__global__ void ln_bf16_kernel(const float* __restrict__ x,
                               const float* __restrict__ gamma,
                               const float* __restrict__ beta,
                               __nv_bfloat16* __restrict__ yh,
                               __nv_bfloat16* __restrict__ yl) {
    const int row = blockIdx.x;
    const int tid = threadIdx.x;
    const float* xr = x + (size_t)row * DD;
    float4 v = *(const float4*)(xr + tid * 4);
    float s  = v.x + v.y + v.z + v.w;
    float ss = v.x*v.x + v.y*v.y + v.z*v.z + v.w*v.w;
    #pragma unroll
    for (int off = 16; off; off >>= 1) {
        s  += __shfl_xor_sync(0xffffffffu, s,  off);
        ss += __shfl_xor_sync(0xffffffffu, ss, off);
    }
    __shared__ float sh[8], sh2[8];
    if ((tid & 31) == 0) { sh[tid >> 5] = s; sh2[tid >> 5] = ss; }
    __syncthreads();
    float tot = 0.f, tot2 = 0.f;
    #pragma unroll
    for (int i = 0; i < 8; i++) { tot += sh[i]; tot2 += sh2[i]; }
    const float mean = tot * (1.f / DD);
    const float var  = tot2 * (1.f / DD) - mean * mean;
    const float inv  = rsqrtf(var + EPSF);
    float4 g = *(const float4*)(gamma + tid * 4);
    float4 b = *(const float4*)(beta  + tid * 4);
    float o0 = g.x * (v.x - mean) * inv + b.x;
    float o1 = g.y * (v.y - mean) * inv + b.y;
    float o2 = g.z * (v.z - mean) * inv + b.z;
    float o3 = g.w * (v.w - mean) * inv + b.w;
    uint32_t h0, l0, h1, l1;
    split2(o0, o1, h0, l0);
    split2(o2, o3, h1, l1);
    uint2 ph = make_uint2(h0, h1), pl = make_uint2(l0, l1);
    *(uint2*)(yh + (size_t)row * DD + tid * 4) = ph;
    *(uint2*)(yl + (size_t)row * DD + tid * 4) = pl;
}

// ======================= tensor-core flash attention =======================
// 128 threads / 4 warps, 64-query tile. Split-bf16 3-pass for both QK and PV.
// Q/K global: [bh][s][dh] split bf16.  V global: [bh][dh][s] split bf16 (transposed).
#define DP 72
#define ATT2_SMEM (6 * 64 * DP * 2)

__global__ __launch_bounds__(128)
void attn_mma(const __nv_bfloat16* __restrict__ Qh_, const __nv_bfloat16* __restrict__ Ql_,
              const __nv_bfloat16* __restrict__ Kh_, const __nv_bfloat16* __restrict__ Kl_,
              const __nv_bfloat16* __restrict__ Vth_, const __nv_bfloat16* __restrict__ Vtl_,
              const int* __restrict__ amask,
              __nv_bfloat16* __restrict__ Oh, __nv_bfloat16* __restrict__ Ol) {
    extern __shared__ __align__(16) __nv_bfloat16 smx[];
    __nv_bfloat16* Qsh = smx;
    __nv_bfloat16* Qsl = Qsh + 64 * DP;
    __nv_bfloat16* Ksh = Qsl + 64 * DP;
    __nv_bfloat16* Ksl = Ksh + 64 * DP;
    __nv_bfloat16* Vsh = Ksl + 64 * DP;   // [dh][key]
    __nv_bfloat16* Vsl = Vsh + 64 * DP;
    __shared__ int mk[64];

    const int qb = blockIdx.x, bh = blockIdx.y, b = bh >> 4, h = bh & 15;
    const int tid = threadIdx.x, lane = tid & 31, w = tid >> 5;
    const int rq = lane >> 2, t2 = (lane & 3) << 1;

    // stage Q tile once
    {
        const __nv_bfloat16* gh = Qh_ + ((size_t)bh * SS + qb * 64) * DHH;
        const __nv_bfloat16* gl = Ql_ + ((size_t)bh * SS + qb * 64) * DHH;
        for (int idx = tid; idx < 64 * 8; idx += 128) {
            const int r = idx >> 3, sg = (idx & 7) << 3;
            *(uint4*)&Qsh[r * DP + sg] = *(const uint4*)(gh + r * DHH + sg);
            *(uint4*)&Qsl[r * DP + sg] = *(const uint4*)(gl + r * DHH + sg);
        }
    }

    float o[8][4];
    #pragma unroll
    for (int i = 0; i < 8; i++) { o[i][0] = o[i][1] = o[i][2] = o[i][3] = 0.f; }
    float m0 = -1e30f, m1 = -1e30f, l0 = 0.f, l1 = 0.f;
    const int rg0 = qb * 64 + (w << 4) + rq;   // global query row (first of pair)

    for (int kb = 0; kb <= qb; kb++) {
        __syncthreads();
        {
            const __nv_bfloat16* gh = Kh_  + ((size_t)bh * SS + kb * 64) * DHH;
            const __nv_bfloat16* gl = Kl_  + ((size_t)bh * SS + kb * 64) * DHH;
            const __nv_bfloat16* vh = Vth_ + ((size_t)bh * DHH) * SS + kb * 64;
            const __nv_bfloat16* vl = Vtl_ + ((size_t)bh * DHH) * SS + kb * 64;
            for (int idx = tid; idx < 64 * 8; idx += 128) {
                const int r = idx >> 3, sg = (idx & 7) << 3;
                *(uint4*)&Ksh[r * DP + sg] = *(const uint4*)(gh + r * DHH + sg);
                *(uint4*)&Ksl[r * DP + sg] = *(const uint4*)(gl + r * DHH + sg);
                *(uint4*)&Vsh[r * DP + sg] = *(const uint4*)(vh + (size_t)r * SS + sg);
                *(uint4*)&Vsl[r * DP + sg] = *(const uint4*)(vl + (size_t)r * SS + sg);
            }
            if (tid < 64) mk[tid] = amask[b * SS + kb * 64 + tid];
        }
        __syncthreads();

        // S = (Qh+Ql) @ (Kh+Kl)^T  (3-pass)
        float s[8][4];
        #pragma unroll
        for (int i = 0; i < 8; i++) { s[i][0] = s[i][1] = s[i][2] = s[i][3] = 0.f; }
        #pragma unroll
        for (int k16 = 0; k16 < 4; k16++) {
            const int ar = (w << 4) + rq;
            const int ac = t2 + (k16 << 4);
            uint32_t ah4[4], al4[4];
            ah4[0] = *(const uint32_t*)&Qsh[ar * DP + ac];
            ah4[1] = *(const uint32_t*)&Qsh[(ar + 8) * DP + ac];
            ah4[2] = *(const uint32_t*)&Qsh[ar * DP + ac + 8];
            ah4[3] = *(const uint32_t*)&Qsh[(ar + 8) * DP + ac + 8];
            al4[0] = *(const uint32_t*)&Qsl[ar * DP + ac];
            al4[1] = *(const uint32_t*)&Qsl[(ar + 8) * DP + ac];
            al4[2] = *(const uint32_t*)&Qsl[ar * DP + ac + 8];
            al4[3] = *(const uint32_t*)&Qsl[(ar + 8) * DP + ac + 8];
            #pragma unroll
            for (int n8 = 0; n8 < 8; n8++) {
                const int br = (n8 << 3) + rq;
                uint32_t bh2[2], bl2[2];
                bh2[0] = *(const uint32_t*)&Ksh[br * DP + ac];
                bh2[1] = *(const uint32_t*)&Ksh[br * DP + ac + 8];
                bl2[0] = *(const uint32_t*)&Ksl[br * DP + ac];
                bl2[1] = *(const uint32_t*)&Ksl[br * DP + ac + 8];
                mma16816(s[n8], ah4, bh2);
                mma16816(s[n8], al4, bh2);
                mma16816(s[n8], ah4, bl2);
            }
        }

        // scale + mask + online softmax (rows r and r+8)
        const bool diag = (kb == qb);
        float rm0 = -1e30f, rm1 = -1e30f;
        #pragma unroll
        for (int n8 = 0; n8 < 8; n8++) {
            const int c0 = (n8 << 3) + t2;
            #pragma unroll
            for (int v = 0; v < 2; v++) {
                const int c = c0 + v;
                const int cgl = kb * 64 + c;
                float x0 = s[n8][v] * 0.125f;
                float x1 = s[n8][2 + v] * 0.125f;
                const bool km = (mk[c] != 0);
                if (!km || (diag && cgl > rg0))     x0 = -1e30f;
                if (!km || (diag && cgl > rg0 + 8)) x1 = -1e30f;
                s[n8][v] = x0; s[n8][2 + v] = x1;
                rm0 = fmaxf(rm0, x0); rm1 = fmaxf(rm1, x1);
            }
        }
        rm0 = fmaxf(rm0, __shfl_xor_sync(0xffffffffu, rm0, 1));
        rm0 = fmaxf(rm0, __shfl_xor_sync(0xffffffffu, rm0, 2));
        rm1 = fmaxf(rm1, __shfl_xor_sync(0xffffffffu, rm1, 1));
        rm1 = fmaxf(rm1, __shfl_xor_sync(0xffffffffu, rm1, 2));
        const float mn0 = fmaxf(m0, rm0), mn1 = fmaxf(m1, rm1);
        const float a0 = __expf(m0 - mn0), a1 = __expf(m1 - mn1);
        float rs0 = 0.f, rs1 = 0.f;
        #pragma unroll
        for (int n8 = 0; n8 < 8; n8++) {
            #pragma unroll
            for (int v = 0; v < 2; v++) {
                float p0 = __expf(s[n8][v] - mn0);
                float p1 = __expf(s[n8][2 + v] - mn1);
                s[n8][v] = p0; s[n8][2 + v] = p1;
                rs0 += p0; rs1 += p1;
            }
        }
        rs0 += __shfl_xor_sync(0xffffffffu, rs0, 1);
        rs0 += __shfl_xor_sync(0xffffffffu, rs0, 2);
        rs1 += __shfl_xor_sync(0xffffffffu, rs1, 1);
        rs1 += __shfl_xor_sync(0xffffffffu, rs1, 2);
        l0 = l0 * a0 + rs0; l1 = l1 * a1 + rs1;
        m0 = mn0; m1 = mn1;
        #pragma unroll
        for (int n8 = 0; n8 < 8; n8++) {
            o[n8][0] *= a0; o[n8][1] *= a0; o[n8][2] *= a1; o[n8][3] *= a1;
        }

        // repack P (C layout) -> A fragments (split bf16), in registers
        uint32_t Ph[4][4], Pl[4][4];
        #pragma unroll
        for (int jj = 0; jj < 4; jj++) {
            const int j0 = jj << 1, j1 = j0 + 1;
            split2(s[j0][0], s[j0][1], Ph[jj][0], Pl[jj][0]);
            split2(s[j0][2], s[j0][3], Ph[jj][1], Pl[jj][1]);
            split2(s[j1][0], s[j1][1], Ph[jj][2], Pl[jj][2]);
            split2(s[j1][2], s[j1][3], Ph[jj][3], Pl[jj][3]);
        }

        // O += (Ph+Pl) @ (Vh+Vl)   (V stored [dh][key] = B operand col-major)
        #pragma unroll
        for (int jj = 0; jj < 4; jj++) {
            const int kc = t2 + (jj << 4);
            #pragma unroll
            for (int n8 = 0; n8 < 8; n8++) {
                const int vr = (n8 << 3) + rq;
                uint32_t vh2[2], vl2[2];
                vh2[0] = *(const uint32_t*)&Vsh[vr * DP + kc];
                vh2[1] = *(const uint32_t*)&Vsh[vr * DP + kc + 8];
                vl2[0] = *(const uint32_t*)&Vsl[vr * DP + kc];
                vl2[1] = *(const uint32_t*)&Vsl[vr * DP + kc + 8];
                mma16816(o[n8], Ph[jj], vh2);
                mma16816(o[n8], Pl[jj], vh2);
                mma16816(o[n8], Ph[jj], vl2);
            }
        }
    }

    // finalize -> split bf16 [B,S,D]
    const float i0 = 1.f / l0, i1 = 1.f / l1;
    const size_t row0 = (size_t)(b * SS) + qb * 64 + (w << 4) + rq;
    #pragma unroll
    for (int n8 = 0; n8 < 8; n8++) {
        const int col = h * DHH + (n8 << 3) + t2;
        uint32_t hh0, ll0, hh1, ll1;
        split2(o[n8][0] * i0, o[n8][1] * i0, hh0, ll0);
        split2(o[n8][2] * i1, o[n8][3] * i1, hh1, ll1);
        *(uint32_t*)(Oh + row0 * DD + col)       = hh0;
        *(uint32_t*)(Ol + row0 * DD + col)       = ll0;
        *(uint32_t*)(Oh + (row0 + 8) * DD + col) = hh1;
        *(uint32_t*)(Ol + (row0 + 8) * DD + col) = ll1;
    }
}

// ======================= host launcher =======================
extern "C" void kernel_launch(void* const* d_in, const int* in_sizes, int n_in,
                              void* d_out, int out_size) {
    const float* x      = (const float*)d_in[0];
    const int*   amask  = (const int*)  d_in[1];
    const float* Wq     = (const float*)d_in[2];
    const float* Wk     = (const float*)d_in[3];
    const float* Wv     = (const float*)d_in[4];
    const float* Wo     = (const float*)d_in[5];
    const float* W1     = (const float*)d_in[6];
    const float* W2     = (const float*)d_in[7];
    const float* gamma1 = (const float*)d_in[8];
    const float* beta1  = (const float*)d_in[9];
    const float* gamma2 = (const float*)d_in[10];
    const float* beta2  = (const float*)d_in[11];
    float* out = (float*)d_out;

    float *p_x1;
    __nv_bfloat16 *p_a1h, *p_a1l, *p_ath, *p_atl, *p_l2h, *p_l2l, *p_gh, *p_gl;
    __nv_bfloat16 *p_qh, *p_ql, *p_kh, *p_kl, *p_vth, *p_vtl;
    __nv_bfloat16 *p_wqh, *p_wql, *p_wkh, *p_wkl, *p_wvh, *p_wvl, *p_woh, *p_wol;
    __nv_bfloat16 *p_w1h, *p_w1l, *p_w2h, *p_w2l;
    cudaGetSymbolAddress((void**)&p_x1,  g_x1);
    cudaGetSymbolAddress((void**)&p_a1h, g_a1h); cudaGetSymbolAddress((void**)&p_a1l, g_a1l);
    cudaGetSymbolAddress((void**)&p_ath, g_ath); cudaGetSymbolAddress((void**)&p_atl, g_atl);
    cudaGetSymbolAddress((void**)&p_l2h, g_l2h); cudaGetSymbolAddress((void**)&p_l2l, g_l2l);
    cudaGetSymbolAddress((void**)&p_gh,  g_gh);  cudaGetSymbolAddress((void**)&p_gl,  g_gl);
    cudaGetSymbolAddress((void**)&p_qh,  g_qh);  cudaGetSymbolAddress((void**)&p_ql,  g_ql);
    cudaGetSymbolAddress((void**)&p_kh,  g_kh);  cudaGetSymbolAddress((void**)&p_kl,  g_kl);
    cudaGetSymbolAddress((void**)&p_vth, g_vth); cudaGetSymbolAddress((void**)&p_vtl, g_vtl);
    cudaGetSymbolAddress((void**)&p_wqh, g_wqh); cudaGetSymbolAddress((void**)&p_wql, g_wql);
    cudaGetSymbolAddress((void**)&p_wkh, g_wkh); cudaGetSymbolAddress((void**)&p_wkl, g_wkl);
    cudaGetSymbolAddress((void**)&p_wvh, g_wvh); cudaGetSymbolAddress((void**)&p_wvl, g_wvl);
    cudaGetSymbolAddress((void**)&p_woh, g_woh); cudaGetSymbolAddress((void**)&p_wol, g_wol);
    cudaGetSymbolAddress((void**)&p_w1h, g_w1h); cudaGetSymbolAddress((void**)&p_w1l, g_w1l);
    cudaGetSymbolAddress((void**)&p_w2h, g_w2h); cudaGetSymbolAddress((void**)&p_w2l, g_w2l);

    cudaFuncSetAttribute(attn_mma, cudaFuncAttributeMaxDynamicSharedMemorySize, ATT2_SMEM);

    // 0. weight transpose + split (Q/K/V/Wo batched; W1 interleaved for fused GLU)
    wt4_kernel<<<dim3(DD/32, DD/32, 4), 256>>>(Wq, Wk, Wv, Wo,
                                               p_wqh, p_wql, p_wkh, p_wkl,
                                               p_wvh, p_wvl, p_woh, p_wol);
    wt_kernel<1><<<dim3(4*DD/32, DD/32),   256>>>(W1, p_w1h, p_w1l, DD,   4*DD);
    wt_kernel<0><<<dim3(DD/32,   2*DD/32), 256>>>(W2, p_w2h, p_w2l, 2*DD, DD);

    // 1. ln1 -> split bf16
    ln_bf16_kernel<<<ROWS, 256>>>(x, gamma1, beta1, p_a1h, p_a1l);
    // 2. merged QKV projection (z selects weight/output; Q,K head layout; V transposed)
    mma_gemm<6><<<dim3(8, 32, 3), 256>>>(p_a1h, p_a1l, p_wqh, p_wql,
                                         nullptr, nullptr, p_qh, p_ql,
                                         p_wkh, p_wkl, p_wvh, p_wvl,
                                         p_kh, p_kl, p_vth, p_vtl, DD, DD);
    // 3. tensor-core causal flash attention -> split bf16 [B,S,D]
    attn_mma<<<dim3(SS/64, BB*HH), 128, ATT2_SMEM>>>(p_qh, p_ql, p_kh, p_kl, p_vth, p_vtl,
                                                     amask, p_ath, p_atl);
    // 4. Wo + residual -> x1
    mma_gemm<2><<<dim3(8, 32), 256>>>(p_ath, p_atl, p_woh, p_wol, p_x1, x, nullptr, nullptr,
                                      nullptr, nullptr, nullptr, nullptr,
                                      nullptr, nullptr, nullptr, nullptr, DD, DD);
    // 5. ln2 -> split bf16
    ln_bf16_kernel<<<ROWS, 256>>>(p_x1, gamma2, beta2, p_l2h, p_l2l);
    // 6. W1 (D -> 4D, interleaved) with fused GLU -> split-bf16 g
    mma_gemm<5><<<dim3(32, 32), 256>>>(p_l2h, p_l2l, p_w1h, p_w1l, nullptr, nullptr, p_gh, p_gl,
                                       nullptr, nullptr, nullptr, nullptr,
                                       nullptr, nullptr, nullptr, nullptr, 4*DD, DD);
    // 7. W2 + residual -> out
    mma_gemm<2><<<dim3(8, 32), 256>>>(p_gh, p_gl, p_w2h, p_w2l, out, p_x1, nullptr, nullptr,
                                      nullptr, nullptr, nullptr, nullptr,
                                      nullptr, nullptr, nullptr, nullptr, DD, 2*DD);
}

// round 16
// speedup vs baseline: 1.6449x; 1.4343x over previous
#include <cuda_runtime.h>
#include <cuda_fp16.h>
#include <cstdint>
#include <math.h>

// Problem constants
#define BB 2
#define SS 2048
#define DD 1024
#define HH 16
#define DHH 64
#define ROWS (BB*SS)        // 4096
#define EPSF 1e-5f

// ======================= scratch (device globals) =======================
__device__ float g_x1  [(size_t)ROWS*DD];

// split-fp16 activations (hi/lo)
__device__ __half g_a1h[(size_t)ROWS*DD],   g_a1l[(size_t)ROWS*DD];
__device__ __half g_ath[(size_t)ROWS*DD],   g_atl[(size_t)ROWS*DD];
__device__ __half g_l2h[(size_t)ROWS*DD],   g_l2l[(size_t)ROWS*DD];
__device__ __half g_gh [(size_t)ROWS*2*DD], g_gl [(size_t)ROWS*2*DD];

// Q hi/lo head-layout [bh][s][dh]; K hi head-layout; V hi transposed [bh][dh][s]
__device__ __half g_qh [(size_t)ROWS*DD], g_ql [(size_t)ROWS*DD];
__device__ __half g_kh [(size_t)ROWS*DD];
__device__ __half g_vth[(size_t)ROWS*DD];

// transposed fp16 (hi-only) weights: [N, K] K-major
__device__ __half g_wqh[(size_t)DD*DD];
__device__ __half g_wkh[(size_t)DD*DD];
__device__ __half g_wvh[(size_t)DD*DD];
__device__ __half g_woh[(size_t)DD*DD];
__device__ __half g_w1h[(size_t)DD*4*DD];
__device__ __half g_w2h[(size_t)2*DD*DD];

__device__ __forceinline__ void f16split(float v, __half& h, __half& l){
    h = __float2half_rn(v);
    l = __float2half_rn(v - __half2float(h));
}
// split a float pair into packed f16x2 hi/lo words (low half = first elem)
__device__ __forceinline__ void split2(float a, float b, uint32_t& hi, uint32_t& lo){
    __half ha = __float2half_rn(a), hb = __float2half_rn(b);
    float ra = a - __half2float(ha), rb = b - __half2float(hb);
    __half la = __float2half_rn(ra), lb = __float2half_rn(rb);
    hi = ((uint32_t)__half_as_ushort(hb) << 16) | (uint32_t)__half_as_ushort(ha);
    lo = ((uint32_t)__half_as_ushort(lb) << 16) | (uint32_t)__half_as_ushort(la);
}

// m16n8k16 fp16 MMA, fp32 accumulate (baseline PTX, works on non-'a' targets)
__device__ __forceinline__ void mma16816(float* c, const uint32_t* a, const uint32_t* b){
    asm volatile(
        "mma.sync.aligned.m16n8k16.row.col.f32.f16.f16.f32 "
        "{%0,%1,%2,%3}, {%4,%5,%6,%7}, {%8,%9}, {%0,%1,%2,%3};"
        : "+f"(c[0]), "+f"(c[1]), "+f"(c[2]), "+f"(c[3])
        : "r"(a[0]), "r"(a[1]), "r"(a[2]), "r"(a[3]), "r"(b[0]), "r"(b[1]));
}

// ======================= split-fp16 2-pass MMA GEMM =======================
// C[M,Nn] = (Ah+Al)[M,K] @ Bh[Nn,K]^T   (B pre-transposed, K-major, hi-only)
// EPI 2: fp32 C = acc + X
// EPI 3: split-fp16 head layout [bh][s][dh] -> CH/CL (Q)
// EPI 7: fp16 hi-only head layout -> CH (K)
// EPI 4: fp16 hi-only transposed head layout [bh][dh][s] -> CH (V)
// EPI 5: fused GLU (W1 columns pre-interleaved left/right) -> split-fp16 g [M, Nn/2]
#define KC 32
#define APAD 40
#define TSTR (128*APAD)    // 5120 halves per tile
// shared: 3 tiles (Ah, Al, Bh) = 15360 halves; EPI5 stage needs 16384
#define GEMM_SH 16384

template<int EPI>
__global__ __launch_bounds__(256)
void mma_gemm(const __half* __restrict__ Ah, const __half* __restrict__ Al,
              const __half* __restrict__ Bh,
              float* __restrict__ C, const float* __restrict__ X,
              __half* __restrict__ CH, __half* __restrict__ CL,
              int Nn, int K) {
    __shared__ __align__(16) __half Ssm[GEMM_SH];
    __half* S0 = Ssm;               // Ah tile
    __half* S1 = Ssm + TSTR;        // Al tile
    __half* S2 = Ssm + 2*TSTR;      // Bh tile

    const int tid  = threadIdx.x;
    const int wid  = tid >> 5, lane = tid & 31;
    const int wm   = wid & 1, wn = wid >> 1;       // warp grid 2(m) x 4(n)
    const int m0   = blockIdx.y << 7, n0 = blockIdx.x << 7;

    const int r_a  = tid >> 1;
    const int c8a  = (tid & 1) << 4;

    float acc[4][4][4];
    #pragma unroll
    for (int mt = 0; mt < 4; mt++)
        #pragma unroll
        for (int nt = 0; nt < 4; nt++)
            #pragma unroll
            for (int j = 0; j < 4; j++) acc[mt][nt][j] = 0.f;

    const int nc = K / KC;
    uint4 sAh[2], sAl[2], sBh[2];

    {
        const __half* pAh = Ah + (size_t)(m0 + r_a) * K + c8a;
        const __half* pAl = Al + (size_t)(m0 + r_a) * K + c8a;
        const __half* pBh = Bh + (size_t)(n0 + r_a) * K + c8a;
        sAh[0] = *(const uint4*)(pAh);     sAh[1] = *(const uint4*)(pAh + 8);
        sAl[0] = *(const uint4*)(pAl);     sAl[1] = *(const uint4*)(pAl + 8);
        sBh[0] = *(const uint4*)(pBh);     sBh[1] = *(const uint4*)(pBh + 8);
    }

    for (int kc = 0; kc < nc; kc++){
        __syncthreads();
        *(uint4*)&S0[r_a * APAD + c8a]     = sAh[0];  *(uint4*)&S0[r_a * APAD + c8a + 8] = sAh[1];
        *(uint4*)&S1[r_a * APAD + c8a]     = sAl[0];  *(uint4*)&S1[r_a * APAD + c8a + 8] = sAl[1];
        *(uint4*)&S2[r_a * APAD + c8a]     = sBh[0];  *(uint4*)&S2[r_a * APAD + c8a + 8] = sBh[1];
        __syncthreads();

        if (kc + 1 < nc){
            const int k0 = (kc + 1) * KC;
            const __half* pAh = Ah + (size_t)(m0 + r_a) * K + k0 + c8a;
            const __half* pAl = Al + (size_t)(m0 + r_a) * K + k0 + c8a;
            const __half* pBh = Bh + (size_t)(n0 + r_a) * K + k0 + c8a;
            sAh[0] = *(const uint4*)(pAh); sAh[1] = *(const uint4*)(pAh + 8);
            sAl[0] = *(const uint4*)(pAl); sAl[1] = *(const uint4*)(pAl + 8);
            sBh[0] = *(const uint4*)(pBh); sBh[1] = *(const uint4*)(pBh + 8);
        }

        #pragma unroll
        for (int ks = 0; ks < 2; ks++){
            const int kb  = ks * 16 + ((lane & 3) << 1);
            const int rq  = lane >> 2;
            uint32_t bh[4][2];
            #pragma unroll
            for (int nt = 0; nt < 4; nt++){
                const int n = (wn << 5) + (nt << 3) + rq;
                bh[nt][0] = *(const uint32_t*)&S2[n * APAD + kb];
                bh[nt][1] = *(const uint32_t*)&S2[n * APAD + kb + 8];
            }
            #pragma unroll
            for (int mt = 0; mt < 4; mt++){
                const int r = (wm << 6) + (mt << 4) + rq;
                uint32_t ah[4], al[4];
                ah[0] = *(const uint32_t*)&S0[r * APAD + kb];
                ah[1] = *(const uint32_t*)&S0[(r + 8) * APAD + kb];
                ah[2] = *(const uint32_t*)&S0[r * APAD + kb + 8];
                ah[3] = *(const uint32_t*)&S0[(r + 8) * APAD + kb + 8];
                al[0] = *(const uint32_t*)&S1[r * APAD + kb];
                al[1] = *(const uint32_t*)&S1[(r + 8) * APAD + kb];
                al[2] = *(const uint32_t*)&S1[r * APAD + kb + 8];
                al[3] = *(const uint32_t*)&S1[(r + 8) * APAD + kb + 8];
                #pragma unroll
                for (int nt = 0; nt < 4; nt++){
                    mma16816(acc[mt][nt], ah, bh[nt]);   // Ah*Bh
                    mma16816(acc[mt][nt], al, bh[nt]);   // Al*Bh
                }
            }
        }
    }

    const int rq = lane >> 2, cg = (lane & 3) << 1;

    if (EPI == 5){
        // fused GLU: fragment pair (n, n+1) = (left, right) via interleaved W1.
        __syncthreads();   // mainloop smem reads complete everywhere
        #pragma unroll
        for (int mt = 0; mt < 4; mt++){
            #pragma unroll
            for (int nt = 0; nt < 4; nt++){
                const int mR = (wm << 6) + (mt << 4) + rq;
                const int cl = ((wn << 5) + (nt << 3) + cg) >> 1;
                const float g0 = acc[mt][nt][0] / (1.f + __expf(-acc[mt][nt][1]));
                const float g1 = acc[mt][nt][2] / (1.f + __expf(-acc[mt][nt][3]));
                __half h_, l_;
                f16split(g0, h_, l_);
                Ssm[mR * 64 + cl] = h_;  Ssm[8192 + mR * 64 + cl] = l_;
                f16split(g1, h_, l_);
                Ssm[(mR + 8) * 64 + cl] = h_;  Ssm[8192 + (mR + 8) * 64 + cl] = l_;
            }
        }
        __syncthreads();
        const int cb = n0 >> 1;                // 64 output cols per CTA
        for (int i = tid; i < 1024; i += 256){ // 128 rows x 8 uint4 segs
            const int row = i >> 3, sg = (i & 7) << 3;
            *(uint4*)(CH + (size_t)(m0 + row) * (2 * DD) + cb + sg) = *(uint4*)&Ssm[row * 64 + sg];
            *(uint4*)(CL + (size_t)(m0 + row) * (2 * DD) + cb + sg) = *(uint4*)&Ssm[8192 + row * 64 + sg];
        }
        return;
    }

    #pragma unroll
    for (int mt = 0; mt < 4; mt++){
        #pragma unroll
        for (int nt = 0; nt < 4; nt++){
            const int m = m0 + (wm << 6) + (mt << 4) + rq;
            const int n = n0 + (wn << 5) + (nt << 3) + cg;
            float2 d01 = make_float2(acc[mt][nt][0], acc[mt][nt][1]);
            float2 d23 = make_float2(acc[mt][nt][2], acc[mt][nt][3]);
            if (EPI == 3){
                const int bb2 = m >> 11, srow = m & 2047, hh2 = n >> 6, dh = n & 63;
                const size_t base = ((size_t)(bb2 * HH + hh2) * SS + srow) * DHH + dh;
                uint32_t h0, l0, h1, l1;
                split2(d01.x, d01.y, h0, l0);
                split2(d23.x, d23.y, h1, l1);
                *(uint32_t*)(CH + base)            = h0;
                *(uint32_t*)(CL + base)            = l0;
                *(uint32_t*)(CH + base + 8 * DHH)  = h1;
                *(uint32_t*)(CL + base + 8 * DHH)  = l1;
            } else if (EPI == 7){
                const int bb2 = m >> 11, srow = m & 2047, hh2 = n >> 6, dh = n & 63;
                const size_t base = ((size_t)(bb2 * HH + hh2) * SS + srow) * DHH + dh;
                __half2 p0 = __floats2half2_rn(d01.x, d01.y);
                __half2 p1 = __floats2half2_rn(d23.x, d23.y);
                *(__half2*)(CH + base)           = p0;
                *(__half2*)(CH + base + 8 * DHH) = p1;
            } else if (EPI == 4){
                const int bb2 = m >> 11, srow = m & 2047, hh2 = n >> 6, dh = n & 63;
                const size_t base = ((size_t)(bb2 * HH + hh2) * DHH + dh) * SS + srow;
                CH[base]          = __float2half_rn(d01.x);
                CH[base + SS]     = __float2half_rn(d01.y);
                CH[base + 8]      = __float2half_rn(d23.x);
                CH[base + SS + 8] = __float2half_rn(d23.y);
            } else {
                const size_t off0 = (size_t)m * Nn + n;
                const size_t off1 = (size_t)(m + 8) * Nn + n;
                if (EPI == 2){
                    float2 x0 = *(const float2*)(X + off0);
                    float2 x1 = *(const float2*)(X + off1);
                    d01.x += x0.x; d01.y += x0.y;
                    d23.x += x1.x; d23.y += x1.y;
                }
                *(float2*)(C + off0) = d01;
                *(float2*)(C + off1) = d23;
            }
        }
    }
}

// ======================= weight transpose (fp16 hi only) ====================
// W [K,N] fp32 row-major -> Th [N,K] fp16 row-major.
// PERM=1 (W1): interleave output rows so GLU left/right pairs are adjacent.
template<int PERM>
__global__ void wt_kernel(const float* __restrict__ W,
                          __half* __restrict__ Th, int K, int N) {
    __shared__ float t[32][33];
    const int n0 = blockIdx.x * 32, k0 = blockIdx.y * 32;
    const int tx = threadIdx.x & 31, ty = threadIdx.x >> 5;
    #pragma unroll
    for (int i = 0; i < 32; i += 8)
        t[ty + i][tx] = W[(size_t)(k0 + ty + i) * N + n0 + tx];
    __syncthreads();
    #pragma unroll
    for (int i = 0; i < 32; i += 8){
        const float v = t[tx][ty + i];
        const int j = n0 + ty + i;
        const int jp = PERM ? ((j < 2 * DD) ? (j << 1) : (((j - 2 * DD) << 1) + 1)) : j;
        Th[(size_t)jp * K + k0 + tx] = __float2half_rn(v);
    }
}

// batched transpose for the four 1024x1024 weights (one launch)
__global__ void wt4_kernel(const float* __restrict__ Wq, const float* __restrict__ Wk,
                           const float* __restrict__ Wv, const float* __restrict__ Wo,
                           __half* qh, __half* kh, __half* vh, __half* oh) {
    __shared__ float t[32][33];
    const float* W; __half* Th;
    switch (blockIdx.z) {
        case 0:  W = Wq; Th = qh; break;
        case 1:  W = Wk; Th = kh; break;
        case 2:  W = Wv; Th = vh; break;
        default: W = Wo; Th = oh; break;
    }
    const int n0 = blockIdx.x * 32, k0 = blockIdx.y * 32;
    const int tx = threadIdx.x & 31, ty = threadIdx.x >> 5;
    #pragma unroll
    for (int i = 0; i < 32; i += 8)
        t[ty + i][tx] = W[(size_t)(k0 + ty + i) * DD + n0 + tx];
    __syncthreads();
    #pragma unroll
    for (int i = 0; i < 32; i += 8)
        Th[(size_t)(n0 + ty + i) * DD + k0 + tx] = __float2half_rn(t[tx][ty + i]);
}

// ======================= LayerNorm -> split fp16 =======================
__global__ void ln_f16_kernel(const float* __restrict__ x,
                              const float* __restrict__ gamma,
                              const float* __restrict__ beta,
                              __half* __restrict__ yh,
                              __half* __restrict__ yl) {
    const int row = blockIdx.x;
    const int tid = threadIdx.x;
    const float* xr = x + (size_t)row * DD;
    float4 v = *(const float4*)(xr + tid * 4);
    float s  = v.x + v.y + v.z + v.w;
    float ss = v.x*v.x + v.y*v.y + v.z*v.z + v.w*v.w;
    #pragma unroll
    for (int off = 16; off; off >>= 1) {
        s  += __shfl_xor_sync(0xffffffffu, s,  off);
        ss += __shfl_xor_sync(0xffffffffu, ss, off);
    }
    __shared__ float sh[8], sh2[8];
    if ((tid & 31) == 0) { sh[tid >> 5] = s; sh2[tid >> 5] = ss; }
    __syncthreads();
    float tot = 0.f, tot2 = 0.f;
    #pragma unroll
    for (int i = 0; i < 8; i++) { tot += sh[i]; tot2 += sh2[i]; }
    const float mean = tot * (1.f / DD);
    const float var  = tot2 * (1.f / DD) - mean * mean;
    const float inv  = rsqrtf(var + EPSF);
    float4 g = *(const float4*)(gamma + tid * 4);
    float4 b = *(const float4*)(beta  + tid * 4);
    float o0 = g.x * (v.x - mean) * inv + b.x;
    float o1 = g.y * (v.y - mean) * inv + b.y;
    float o2 = g.z * (v.z - mean) * inv + b.z;
    float o3 = g.w * (v.w - mean) * inv + b.w;
    uint32_t h0, l0, h1, l1;
    split2(o0, o1, h0, l0);
    split2(o2, o3, h1, l1);
    uint2 ph = make_uint2(h0, h1), pl = make_uint2(l0, l1);
    *(uint2*)(yh + (size_t)row * DD + tid * 4) = ph;
    *(uint2*)(yl + (size_t)row * DD + tid * 4) = pl;
}

// ======================= tensor-core flash attention =======================
// 128 threads / 4 warps, 64-query tile. Split-fp16 2-pass for QK and PV.
// Q: hi+lo [bh][s][dh].  K: hi [bh][s][dh].  V: hi transposed [bh][dh][s].
#define DP 72
#define ATT2_SMEM (4 * 64 * DP * 2)

__global__ __launch_bounds__(128)
void attn_mma(const __half* __restrict__ Qh_, const __half* __restrict__ Ql_,
              const __half* __restrict__ Kh_, const __half* __restrict__ Vth_,
              const int* __restrict__ amask,
              __half* __restrict__ Oh, __half* __restrict__ Ol) {
    extern __shared__ __align__(16) __half smx[];
    __half* Qsh = smx;
    __half* Qsl = Qsh + 64 * DP;
    __half* Ksh = Qsl + 64 * DP;
    __half* Vsh = Ksh + 64 * DP;   // [dh][key]
    __shared__ int mk[64];

    const int qb = blockIdx.x, bh = blockIdx.y, b = bh >> 4, h = bh & 15;
    const int tid = threadIdx.x, lane = tid & 31, w = tid >> 5;
    const int rq = lane >> 2, t2 = (lane & 3) << 1;

    // stage Q tile once
    {
        const __half* gh = Qh_ + ((size_t)bh * SS + qb * 64) * DHH;
        const __half* gl = Ql_ + ((size_t)bh * SS + qb * 64) * DHH;
        for (int idx = tid; idx < 64 * 8; idx += 128) {
            const int r = idx >> 3, sg = (idx & 7) << 3;
            *(uint4*)&Qsh[r * DP + sg] = *(const uint4*)(gh + r * DHH + sg);
            *(uint4*)&Qsl[r * DP + sg] = *(const uint4*)(gl + r * DHH + sg);
        }
    }

    float o[8][4];
    #pragma unroll
    for (int i = 0; i < 8; i++) { o[i][0] = o[i][1] = o[i][2] = o[i][3] = 0.f; }
    float m0 = -1e30f, m1 = -1e30f, l0 = 0.f, l1 = 0.f;
    const int rg0 = qb * 64 + (w << 4) + rq;   // global query row (first of pair)

    for (int kb = 0; kb <= qb; kb++) {
        __syncthreads();
        {
            const __half* gh = Kh_  + ((size_t)bh * SS + kb * 64) * DHH;
            const __half* vh = Vth_ + ((size_t)bh * DHH) * SS + kb * 64;
            for (int idx = tid; idx < 64 * 8; idx += 128) {
                const int r = idx >> 3, sg = (idx & 7) << 3;
                *(uint4*)&Ksh[r * DP + sg] = *(const uint4*)(gh + r * DHH + sg);
                *(uint4*)&Vsh[r * DP + sg] = *(const uint4*)(vh + (size_t)r * SS + sg);
            }
            if (tid < 64) mk[tid] = amask[b * SS + kb * 64 + tid];
        }
        __syncthreads();

        // S = (Qh+Ql) @ Kh^T  (2-pass)
        float s[8][4];
        #pragma unroll
        for (int i = 0; i < 8; i++) { s[i][0] = s[i][1] = s[i][2] = s[i][3] = 0.f; }
        #pragma unroll
        for (int k16 = 0; k16 < 4; k16++) {
            const int ar = (w << 4) + rq;
            const int ac = t2 + (k16 << 4);
            uint32_t ah4[4], al4[4];
            ah4[0] = *(const uint32_t*)&Qsh[ar * DP + ac];
            ah4[1] = *(const uint32_t*)&Qsh[(ar + 8) * DP + ac];
            ah4[2] = *(const uint32_t*)&Qsh[ar * DP + ac + 8];
            ah4[3] = *(const uint32_t*)&Qsh[(ar + 8) * DP + ac + 8];
            al4[0] = *(const uint32_t*)&Qsl[ar * DP + ac];
            al4[1] = *(const uint32_t*)&Qsl[(ar + 8) * DP + ac];
            al4[2] = *(const uint32_t*)&Qsl[ar * DP + ac + 8];
            al4[3] = *(const uint32_t*)&Qsl[(ar + 8) * DP + ac + 8];
            #pragma unroll
            for (int n8 = 0; n8 < 8; n8++) {
                const int br = (n8 << 3) + rq;
                uint32_t bh2[2];
                bh2[0] = *(const uint32_t*)&Ksh[br * DP + ac];
                bh2[1] = *(const uint32_t*)&Ksh[br * DP + ac + 8];
                mma16816(s[n8], ah4, bh2);
                mma16816(s[n8], al4, bh2);
            }
        }

        // scale + mask + online softmax (rows r and r+8)
        const bool diag = (kb == qb);
        float rm0 = -1e30f, rm1 = -1e30f;
        #pragma unroll
        for (int n8 = 0; n8 < 8; n8++) {
            const int c0 = (n8 << 3) + t2;
            #pragma unroll
            for (int v = 0; v < 2; v++) {
                const int c = c0 + v;
                const int cgl = kb * 64 + c;
                float x0 = s[n8][v] * 0.125f;
                float x1 = s[n8][2 + v] * 0.125f;
                const bool km = (mk[c] != 0);
                if (!km || (diag && cgl > rg0))     x0 = -1e30f;
                if (!km || (diag && cgl > rg0 + 8)) x1 = -1e30f;
                s[n8][v] = x0; s[n8][2 + v] = x1;
                rm0 = fmaxf(rm0, x0); rm1 = fmaxf(rm1, x1);
            }
        }
        rm0 = fmaxf(rm0, __shfl_xor_sync(0xffffffffu, rm0, 1));
        rm0 = fmaxf(rm0, __shfl_xor_sync(0xffffffffu, rm0, 2));
        rm1 = fmaxf(rm1, __shfl_xor_sync(0xffffffffu, rm1, 1));
        rm1 = fmaxf(rm1, __shfl_xor_sync(0xffffffffu, rm1, 2));
        const float mn0 = fmaxf(m0, rm0), mn1 = fmaxf(m1, rm1);
        const float a0 = __expf(m0 - mn0), a1 = __expf(m1 - mn1);
        float rs0 = 0.f, rs1 = 0.f;
        #pragma unroll
        for (int n8 = 0; n8 < 8; n8++) {
            #pragma unroll
            for (int v = 0; v < 2; v++) {
                float p0 = __expf(s[n8][v] - mn0);
                float p1 = __expf(s[n8][2 + v] - mn1);
                s[n8][v] = p0; s[n8][2 + v] = p1;
                rs0 += p0; rs1 += p1;
            }
        }
        rs0 += __shfl_xor_sync(0xffffffffu, rs0, 1);
        rs0 += __shfl_xor_sync(0xffffffffu, rs0, 2);
        rs1 += __shfl_xor_sync(0xffffffffu, rs1, 1);
        rs1 += __shfl_xor_sync(0xffffffffu, rs1, 2);
        l0 = l0 * a0 + rs0; l1 = l1 * a1 + rs1;
        m0 = mn0; m1 = mn1;
        #pragma unroll
        for (int n8 = 0; n8 < 8; n8++) {
            o[n8][0] *= a0; o[n8][1] *= a0; o[n8][2] *= a1; o[n8][3] *= a1;
        }

        // repack P (C layout) -> A fragments (split fp16), in registers
        uint32_t Ph[4][4], Pl[4][4];
        #pragma unroll
        for (int jj = 0; jj < 4; jj++) {
            const int j0 = jj << 1, j1 = j0 + 1;
            split2(s[j0][0], s[j0][1], Ph[jj][0], Pl[jj][0]);
            split2(s[j0][2], s[j0][3], Ph[jj][1], Pl[jj][1]);
            split2(s[j1][0], s[j1][1], Ph[jj][2], Pl[jj][2]);
            split2(s[j1][2], s[j1][3], Ph[jj][3], Pl[jj][3]);
        }

        // O += (Ph+Pl) @ Vh   (V stored [dh][key] = B operand col-major)
        #pragma unroll
        for (int jj = 0; jj < 4; jj++) {
            const int kc = t2 + (jj << 4);
            #pragma unroll
            for (int n8 = 0; n8 < 8; n8++) {
                const int vr = (n8 << 3) + rq;
                uint32_t vh2[2];
                vh2[0] = *(const uint32_t*)&Vsh[vr * DP + kc];
                vh2[1] = *(const uint32_t*)&Vsh[vr * DP + kc + 8];
                mma16816(o[n8], Ph[jj], vh2);
                mma16816(o[n8], Pl[jj], vh2);
            }
        }
    }

    // finalize -> split fp16 [B,S,D]
    const float i0 = 1.f / l0, i1 = 1.f / l1;
    const size_t row0 = (size_t)(b * SS) + qb * 64 + (w << 4) + rq;
    #pragma unroll
    for (int n8 = 0; n8 < 8; n8++) {
        const int col = h * DHH + (n8 << 3) + t2;
        uint32_t hh0, ll0, hh1, ll1;
        split2(o[n8][0] * i0, o[n8][1] * i0, hh0, ll0);
        split2(o[n8][2] * i1, o[n8][3] * i1, hh1, ll1);
        *(uint32_t*)(Oh + row0 * DD + col)       = hh0;
        *(uint32_t*)(Ol + row0 * DD + col)       = ll0;
        *(uint32_t*)(Oh + (row0 + 8) * DD + col) = hh1;
        *(uint32_t*)(Ol + (row0 + 8) * DD + col) = ll1;
    }
}

// ======================= host launcher =======================
extern "C" void kernel_launch(void* const* d_in, const int* in_sizes, int n_in,
                              void* d_out, int out_size) {
    const float* x      = (const float*)d_in[0];
    const int*   amask  = (const int*)  d_in[1];
    const float* Wq     = (const float*)d_in[2];
    const float* Wk     = (const float*)d_in[3];
    const float* Wv     = (const float*)d_in[4];
    const float* Wo     = (const float*)d_in[5];
    const float* W1     = (const float*)d_in[6];
    const float* W2     = (const float*)d_in[7];
    const float* gamma1 = (const float*)d_in[8];
    const float* beta1  = (const float*)d_in[9];
    const float* gamma2 = (const float*)d_in[10];
    const float* beta2  = (const float*)d_in[11];
    float* out = (float*)d_out;

    float *p_x1;
    __half *p_a1h, *p_a1l, *p_ath, *p_atl, *p_l2h, *p_l2l, *p_gh, *p_gl;
    __half *p_qh, *p_ql, *p_kh, *p_vth;
    __half *p_wqh, *p_wkh, *p_wvh, *p_woh, *p_w1h, *p_w2h;
    cudaGetSymbolAddress((void**)&p_x1,  g_x1);
    cudaGetSymbolAddress((void**)&p_a1h, g_a1h); cudaGetSymbolAddress((void**)&p_a1l, g_a1l);
    cudaGetSymbolAddress((void**)&p_ath, g_ath); cudaGetSymbolAddress((void**)&p_atl, g_atl);
    cudaGetSymbolAddress((void**)&p_l2h, g_l2h); cudaGetSymbolAddress((void**)&p_l2l, g_l2l);
    cudaGetSymbolAddress((void**)&p_gh,  g_gh);  cudaGetSymbolAddress((void**)&p_gl,  g_gl);
    cudaGetSymbolAddress((void**)&p_qh,  g_qh);  cudaGetSymbolAddress((void**)&p_ql,  g_ql);
    cudaGetSymbolAddress((void**)&p_kh,  g_kh);
    cudaGetSymbolAddress((void**)&p_vth, g_vth);
    cudaGetSymbolAddress((void**)&p_wqh, g_wqh);
    cudaGetSymbolAddress((void**)&p_wkh, g_wkh);
    cudaGetSymbolAddress((void**)&p_wvh, g_wvh);
    cudaGetSymbolAddress((void**)&p_woh, g_woh);
    cudaGetSymbolAddress((void**)&p_w1h, g_w1h);
    cudaGetSymbolAddress((void**)&p_w2h, g_w2h);

    cudaFuncSetAttribute(attn_mma, cudaFuncAttributeMaxDynamicSharedMemorySize, ATT2_SMEM);

    // 0. weight transpose (fp16 hi only; W1 interleaved for fused GLU)
    wt4_kernel<<<dim3(DD/32, DD/32, 4), 256>>>(Wq, Wk, Wv, Wo, p_wqh, p_wkh, p_wvh, p_woh);
    wt_kernel<1><<<dim3(4*DD/32, DD/32),   256>>>(W1, p_w1h, DD,   4*DD);
    wt_kernel<0><<<dim3(DD/32,   2*DD/32), 256>>>(W2, p_w2h, 2*DD, DD);

    // 1. ln1 -> split fp16
    ln_f16_kernel<<<ROWS, 256>>>(x, gamma1, beta1, p_a1h, p_a1l);
    // 2. QKV projections (Q hi+lo head layout; K hi head layout; V hi transposed)
    mma_gemm<3><<<dim3(8, 32), 256>>>(p_a1h, p_a1l, p_wqh, nullptr, nullptr, p_qh, p_ql, DD, DD);
    mma_gemm<7><<<dim3(8, 32), 256>>>(p_a1h, p_a1l, p_wkh, nullptr, nullptr, p_kh, nullptr, DD, DD);
    mma_gemm<4><<<dim3(8, 32), 256>>>(p_a1h, p_a1l, p_wvh, nullptr, nullptr, p_vth, nullptr, DD, DD);
    // 3. tensor-core causal flash attention -> split fp16 [B,S,D]
    attn_mma<<<dim3(SS/64, BB*HH), 128, ATT2_SMEM>>>(p_qh, p_ql, p_kh, p_vth,
                                                     amask, p_ath, p_atl);
    // 4. Wo + residual -> x1
    mma_gemm<2><<<dim3(8, 32), 256>>>(p_ath, p_atl, p_woh, p_x1, x, nullptr, nullptr, DD, DD);
    // 5. ln2 -> split fp16
    ln_f16_kernel<<<ROWS, 256>>>(p_x1, gamma2, beta2, p_l2h, p_l2l);
    // 6. W1 (D -> 4D, interleaved) with fused GLU -> split-fp16 g
    mma_gemm<5><<<dim3(32, 32), 256>>>(p_l2h, p_l2l, p_w1h, nullptr, nullptr, p_gh, p_gl, 4*DD, DD);
    // 7. W2 + residual -> out
    mma_gemm<2><<<dim3(8, 32), 256>>>(p_gh, p_gl, p_w2h, out, p_x1, nullptr, nullptr, DD, 2*DD);
}